// round 14
// baseline (speedup 1.0000x reference)
#include <cuda_runtime.h>
#include <cstdint>
#include <math.h>

// ---------------- problem constants ----------------
#define NNODE 2048
#define NEDGE 4096
#define LF    49
#define LR    16
#define MMID  25
#define NYR   3
#define CCH   128
#define HID   128
#define XLC   (LF*CCH)      // 6272
#define FEATW 2064          // 16*129
#define MSGW  2048          // 16*128
#define TPAD  1280          // padded 1225
#define KCG   64            // padded 49

// ---------------- device scratch ----------------
__device__ __align__(16) float g_WdT  [128*128];
__device__ __align__(16) float g_Wn1aT[128*FEATW];
__device__ __align__(16) float g_Wn1bT[2048*128];
__device__ __align__(16) float g_Wn2aT[128*FEATW];
__device__ __align__(16) float g_Wn2bT[2048*128];
__device__ __align__(16) float g_Wp1T [128*2048];
__device__ __align__(16) float g_Wp2T [2048*128];
__device__ __align__(16) float g_Wc1T [TPAD*KCG];
__device__ __align__(16) float g_Wc2T [TPAD*KCG];
__device__ __align__(16) float g_Wc3T [TPAD*KCG];
__device__ __align__(16) float g_xer  [NEDGE*128];
__device__ __align__(16) float g_xe   [NEDGE*HID];
__device__ __align__(16) float g_nm   [NNODE*KCG];
__device__ __align__(16) float g_t3   [3*NEDGE*TPAD];
__device__ __align__(16) float g_A    [NEDGE*LF];
__device__ __align__(16) float g_feat [2*NEDGE*FEATW];
__device__ __align__(16) float g_h    [2*NEDGE*HID];
__device__ __align__(16) float g_h2   [2*NEDGE*MSGW];
__device__ __align__(16) float g_msg  [NEDGE*NYR*MSGW];
__device__ __align__(16) float g_m1   [NEDGE*NYR*HID];
__device__ __align__(16) float g_m2   [NEDGE*NYR*MSGW];
__device__ __align__(16) float g_part [4*12288*128];

__device__ __forceinline__ float silu_f(float v) { return v / (1.0f + __expf(-v)); }

__device__ __forceinline__ float rtf(float f) {
    uint32_t r;
    asm("cvt.rna.tf32.f32 %0, %1;" : "=r"(r) : "f"(f));
    return __uint_as_float(r);
}

__device__ __forceinline__ void mma8(float* d, uint32_t a0, uint32_t a1, uint32_t a2,
                                     uint32_t a3, uint32_t b0, uint32_t b1) {
    asm volatile(
        "mma.sync.aligned.m16n8k8.row.col.f32.tf32.tf32.f32 "
        "{%0,%1,%2,%3}, {%4,%5,%6,%7}, {%8,%9}, {%0,%1,%2,%3};"
        : "+f"(d[0]), "+f"(d[1]), "+f"(d[2]), "+f"(d[3])
        : "r"(a0), "r"(a1), "r"(a2), "r"(a3), "r"(b0), "r"(b1));
}

__device__ __forceinline__ void cp16(uint32_t dst, const float* src, bool pred) {
    int sz = pred ? 16 : 0;
    asm volatile("cp.async.cg.shared.global [%0], [%1], 16, %2;"
                 :: "r"(dst), "l"(src), "r"(sz) : "memory");
}
#define CP_COMMIT() asm volatile("cp.async.commit_group;" ::: "memory")
template<int N> __device__ __forceinline__ void cpwait() {
    asm volatile("cp.async.wait_group %0;" :: "n"(N) : "memory");
}

// ---------------------------------------------------------------------------
// Unified job-based tf32 GEMM. Each blockIdx.z selects a GJob; CTAs outside
// the job's M/N range exit early (uniform branch, before any barrier).
// Body identical to R11-proven 128-thread 64x64-warp-tile double-buffer loop.
// epi: 0=raw, 1=bias+silu. Dual-B/bias keyed on blockIdx.y < ysplit.
// rmap (optional) maps logical A row -> source row.
// ---------------------------------------------------------------------------
#define LDA 36
#define ATILE (128*LDA)
#define BUFSZ (2*ATILE)
#define DYN_SMEM (2*BUFSZ*4)     // 73728 bytes per CTA; occ 2

struct GJob {
    const float* A; const float* BT0; const float* BT1;
    const float* bias0; const float* bias1;
    const int* rmap; float* C;
    int M, Nreal, K, ldc, c0, cend, ysplit, epi;
};
struct GPack { GJob j[8]; };

__global__ __launch_bounds__(128, 2)
void tgemm(GPack P)
{
    const GJob J = P.j[blockIdx.z];
    const int bm0 = blockIdx.y * 128;
    const int bn0 = blockIdx.x * 128;
    if (bm0 >= J.M || bn0 >= J.Nreal) return;

    extern __shared__ uint32_t sm[];
    const uint32_t smBase = (uint32_t)__cvta_generic_to_shared(sm);
    const int tid  = threadIdx.x;
    const int lane = tid & 31;
    const int warp = tid >> 5;
    const int wm = warp >> 1, wn = warp & 1;
    const int g = lane >> 2, t = lane & 3;

    const float* A  = J.A;
    const float* BT = ((int)blockIdx.y < J.ysplit) ? J.BT0 : J.BT1;
    const float* bias = ((int)blockIdx.y < J.ysplit) ? J.bias0 : J.bias1;
    const int* rmap = J.rmap;
    const int K = J.K, Nreal = J.Nreal;
    const int c0 = J.c0, cend = J.cend;

    float acc[4][8][4];
#pragma unroll
    for (int i = 0; i < 4; i++)
#pragma unroll
        for (int j = 0; j < 8; j++)
#pragma unroll
            for (int q = 0; q < 4; q++) acc[i][j][q] = 0.0f;

    const int lseg = tid & 7;

    auto issue = [&](int c, int b) {
        const int kbase = c * 32;
        const int gk = kbase + lseg * 4;
        const bool kok = gk < K;
        uint32_t As = smBase + (uint32_t)(b * BUFSZ) * 4;
        uint32_t Bs = As + ATILE * 4;
#pragma unroll
        for (int i = 0; i < 8; i++) {
            int idx = tid + i * 128;
            int r = idx >> 3;
            int grow = bm0 + r;
            size_t srow = rmap ? (size_t)rmap[grow] : (size_t)grow;
            cp16(As + (uint32_t)(r * LDA + lseg * 4) * 4,
                 A + srow * K + gk, kok);
        }
#pragma unroll
        for (int i = 0; i < 8; i++) {
            int idx = tid + i * 128;
            int r = idx >> 3;
            int gn = bn0 + r;
            cp16(Bs + (uint32_t)(r * LDA + lseg * 4) * 4,
                 BT + (size_t)gn * K + gk, kok && (gn < Nreal));
        }
        CP_COMMIT();
    };

    issue(c0, 0);
    for (int c = c0; c < cend; ++c) {
        int b = (c - c0) & 1;
        if (c + 1 < cend) { issue(c + 1, b ^ 1); cpwait<1>(); }
        else              { cpwait<0>(); }
        __syncthreads();

        const uint32_t* As = sm + b * BUFSZ;
        const uint32_t* Bs = As + ATILE;

        uint32_t af[2][4][4], bf[2][8][2];
        auto loadfrag = [&](int kk, int buf) {
            const int k0 = kk * 8;
#pragma unroll
            for (int i = 0; i < 4; i++) {
                int mb = wm * 64 + i * 16;
                af[buf][i][0] = As[(mb + g)     * LDA + k0 + t];
                af[buf][i][1] = As[(mb + g + 8) * LDA + k0 + t];
                af[buf][i][2] = As[(mb + g)     * LDA + k0 + t + 4];
                af[buf][i][3] = As[(mb + g + 8) * LDA + k0 + t + 4];
            }
#pragma unroll
            for (int j = 0; j < 8; j++) {
                int nb = wn * 64 + j * 8;
                bf[buf][j][0] = Bs[(nb + g) * LDA + k0 + t];
                bf[buf][j][1] = Bs[(nb + g) * LDA + k0 + t + 4];
            }
        };

        loadfrag(0, 0);
#pragma unroll
        for (int kk = 0; kk < 4; kk++) {
            int cur = kk & 1;
            if (kk < 3) loadfrag(kk + 1, cur ^ 1);
#pragma unroll
            for (int i = 0; i < 4; i++)
#pragma unroll
                for (int j = 0; j < 8; j++)
                    mma8(acc[i][j], af[cur][i][0], af[cur][i][1],
                         af[cur][i][2], af[cur][i][3],
                         bf[cur][j][0], bf[cur][j][1]);
        }
        __syncthreads();
    }

    float* Cz = J.C;
#pragma unroll
    for (int i = 0; i < 4; i++) {
        int r0 = bm0 + wm * 64 + i * 16 + g;
#pragma unroll
        for (int j = 0; j < 8; j++) {
            int cc = bn0 + wn * 64 + j * 8 + 2 * t;
#pragma unroll
            for (int half = 0; half < 2; half++) {
                int row = r0 + half * 8;
                float v0 = acc[i][j][half * 2 + 0];
                float v1 = acc[i][j][half * 2 + 1];
                if (cc < Nreal) {
                    if (J.epi) {
                        v0 = silu_f(v0 + bias[cc]);
                        v1 = (cc + 1 < Nreal) ? silu_f(v1 + bias[cc + 1]) : 0.0f;
                    }
                    float* cp = Cz + (size_t)row * J.ldc + cc;
                    if (cc + 1 < Nreal) { float2 fv = make_float2(v0, v1); *(float2*)cp = fv; }
                    else cp[0] = v0;
                }
            }
        }
    }
}

// ---------------------------------------------------------------------------
// merged: combine<1> (blocks 0..4095) + midcon (blocks 4096..8191), 256 thr
// ---------------------------------------------------------------------------
__global__ void k_combmid(const float* __restrict__ part, const float* __restrict__ bias0,
                          const float* __restrict__ bias1, float* __restrict__ outp,
                          const float* __restrict__ nm, const int* __restrict__ eidx,
                          const float* __restrict__ t1, const float* __restrict__ t2,
                          const float* __restrict__ t3, float* __restrict__ Aout)
{
    int bid = blockIdx.x, tid = threadIdx.x;
    if (bid < 4096) {
        // k_combine<1>: M = 2*NEDGE, nsplit 4, Mhalf NEDGE
        int idx = bid * 256 + tid;
        int m = idx >> 7, n = idx & 127;
        float s = (m < NEDGE) ? bias0[n] : bias1[n];
#pragma unroll
        for (int zz = 0; zz < 4; zz++)
            s += part[(size_t)zz * 2 * NEDGE * 128 + idx];
        s = silu_f(s);
        outp[idx] = rtf(s);
    } else {
        int e = bid - 4096;
        __shared__ float ys[LF];
        __shared__ float ms[MMID];
        int dst = eidx[NEDGE + e];
        if (tid < LF) ys[tid] = nm[dst * KCG + tid];
        __syncthreads();
        if (tid < MMID) {
            const float* tp = t1 + (size_t)e * TPAD + tid;
            float s = 0.0f;
#pragma unroll
            for (int j = 0; j < LF; j++) s = fmaf(ys[j], tp[j * MMID], s);
            ms[tid] = s;
        }
        __syncthreads();
        if (tid < LF) {
            const float* tp2 = t2 + (size_t)e * TPAD + tid;
            const float* tp3 = t3 + (size_t)e * TPAD + tid;
            float s = 0.0f;
#pragma unroll
            for (int j = 0; j < MMID; j++)
                s = fmaf(ms[j], tp2[j * LF] + tp3[j * LF], s);
            Aout[e * LF + tid] = s;
        }
    }
}

// combine<2> for the edge-MLP stage
__global__ void k_combine2(const float* __restrict__ part, const float* __restrict__ bias,
                           const float* __restrict__ xe, float* __restrict__ outp, int M)
{
    int idx = blockIdx.x * 256 + threadIdx.x;
    if (idx >= M * 128) return;
    int m = idx >> 7, n = idx & 127;
    float s = bias[n];
#pragma unroll
    for (int zz = 0; zz < 2; zz++) s += part[(size_t)zz * M * 128 + idx];
    s = silu_f(s);
    s *= xe[(size_t)(m / 3) * 128 + n];
    outp[idx] = rtf(s);
}

// ---------------- fused multi-transpose + copy-round (ldD==0) ---------------
struct TD { const float* src; float* dst; int R, C, ldD, tilesX, tileOff; };
struct TDPack { TD d[11]; };

__global__ void k_tmulti(TDPack P, int ndesc)
{
    __shared__ float smt[32][33];
    int bid = blockIdx.x;
    int di = 0;
    for (int i = 1; i < ndesc; i++) if (bid >= P.d[i].tileOff) di = i;
    const TD& D = P.d[di];
    int ti = bid - D.tileOff;
    int c0 = (ti % D.tilesX) * 32;
    int r0 = (ti / D.tilesX) * 32;
    int tx = threadIdx.x & 31, ty = threadIdx.x >> 5;
    if (D.ldD == 0) {
        // elementwise tf32 round-copy
#pragma unroll
        for (int i = 0; i < 4; i++) {
            int r = r0 + ty + i * 8, c = c0 + tx;
            if (r < D.R && c < D.C)
                D.dst[(size_t)r * D.C + c] = rtf(D.src[(size_t)r * D.C + c]);
        }
        __syncthreads();
        return;
    }
#pragma unroll
    for (int i = 0; i < 4; i++) {
        int r = r0 + ty + i * 8, c = c0 + tx;
        smt[ty + i * 8][tx] = (r < D.R && c < D.C) ? rtf(D.src[(size_t)r * D.C + c]) : 0.0f;
    }
    __syncthreads();
#pragma unroll
    for (int i = 0; i < 4; i++) {
        int c = c0 + ty + i * 8, r = r0 + tx;
        if (c < D.C && r < D.ldD) D.dst[(size_t)c * D.ldD + r] = smt[tx][ty + i * 8];
    }
}

// ---------------------------------------------------------------------------
// merged per-edge feat (blocks 0..8191) + per-node mean (blocks 8192..10239)
// ---------------------------------------------------------------------------
__global__ void k_featnm(const float* __restrict__ x, const float* __restrict__ glovec,
                         const float* __restrict__ wign, const int* __restrict__ eidx,
                         float* __restrict__ feat, float* __restrict__ nm)
{
    int bid = blockIdx.x, tid = threadIdx.x;
    int lane = tid & 31, warp = tid >> 5;
    if (bid >= 2 * NEDGE) {
        int n = bid - 2 * NEDGE;
        const float4* p = (const float4*)(x + (size_t)n * XLC);
        if (tid >= 49 && tid < 64) nm[n * KCG + tid] = 0.f;
        for (int l = warp; l < LF; l += 4) {
            float4 a = p[l * 32 + lane];
            float s = (a.x + a.y) + (a.z + a.w);
#pragma unroll
            for (int o = 16; o > 0; o >>= 1)
                s += __shfl_xor_sync(0xffffffffu, s, o);
            if (lane == 0) nm[n * KCG + l] = rtf(s * (1.0f / 128.0f));
        }
        return;
    }
    int e2 = bid;
    int half = e2 >> 12;
    int e = e2 & 4095;
    __shared__ float wigS[256];
    __shared__ float gS[16];
    __shared__ float red[64];
    int node  = eidx[half ? (NEDGE + e) : e];
    int other = eidx[half ? e : (NEDGE + e)];
    wigS[tid]       = wign[e * 256 + tid];
    wigS[tid + 128] = wign[e * 256 + 128 + tid];
    if (tid < 16) gS[tid] = glovec[other * LR + tid];
    __syncthreads();

    float xr[16];
    const float* xp = x + (size_t)node * XLC;
#pragma unroll
    for (int j = 0; j < 16; j++) xr[j] = xp[j * 128 + tid];

    float* fp = feat + (size_t)e2 * FEATW;
#pragma unroll
    for (int i = 0; i < 16; i++) {
        float a = 0.0f;
#pragma unroll
        for (int j = 0; j < 16; j++) a = fmaf(wigS[j * 16 + i], xr[j], a);
        fp[i * 129 + tid] = rtf(a);
        float s = a;
#pragma unroll
        for (int o = 16; o > 0; o >>= 1) s += __shfl_xor_sync(0xffffffffu, s, o);
        if (lane == 0) red[i * 4 + warp] = s;
    }
    __syncthreads();
    if (tid < 16) {
        float s = red[tid * 4] + red[tid * 4 + 1] + red[tid * 4 + 2] + red[tid * 4 + 3];
        fp[tid * 129 + 128] = rtf(s * (1.0f / 128.0f) * gS[tid]);
    }
}

// fused: sh compute + z-build + wigner rotate
__global__ __launch_bounds__(256)
void k_rotmsg(const float* __restrict__ x, const int* __restrict__ eidx,
              const float* __restrict__ Aarr, const float* __restrict__ h2,
              const float* __restrict__ wign, const float* __restrict__ wigner,
              float* __restrict__ msg)
{
    int e = blockIdx.x, tid = threadIdx.x;
    __shared__ float zs[LF * 128];
    __shared__ float wgS[48 * 49];
    __shared__ float As_[LF];
    __shared__ float wigS[256];
    int src = eidx[e], dst = eidx[NEDGE + e];
    const float4* xs4 = (const float4*)(x + (size_t)src * XLC);
    const float4* xt4 = (const float4*)(x + (size_t)dst * XLC);
    wigS[tid] = wign[e * 256 + tid];
    if (tid < LF) As_[tid] = Aarr[e * LF + tid];
    __syncthreads();

    float4* zs4 = (float4*)zs;
    for (int i4 = tid; i4 < LF * 32; i4 += 256) {
        int l = i4 >> 5;
        float4 a = xs4[i4], b = xt4[i4];
        float al = As_[l];
        float4 v;
        v.x = 2.0f * (a.x + b.x) + al;
        v.y = 2.0f * (a.y + b.y) + al;
        v.z = 2.0f * (a.z + b.z) + al;
        v.w = 2.0f * (a.w + b.w) + al;
        zs4[i4] = v;
    }
    const float4* wp4 = (const float4*)(wigner + (size_t)e * (48 * 49));
    float4* wg4 = (float4*)wgS;
    for (int i4 = tid; i4 < 588; i4 += 256) wg4[i4] = wp4[i4];
    __syncthreads();

    if (tid < 128) {
        float hr[16];
        const float* hpa = h2 + (size_t)e * MSGW;
        const float* hpb = h2 + (size_t)(e + NEDGE) * MSGW;
#pragma unroll
        for (int j = 0; j < 16; j++) hr[j] = hpa[j * 128 + tid] + hpb[j * 128 + tid];
#pragma unroll
        for (int i = 0; i < 16; i++) {
            float s = 0.0f;
#pragma unroll
            for (int j = 0; j < 16; j++) s = fmaf(wigS[i * 16 + j], hr[j], s);
            zs[i * 128 + tid] += s;
        }
    }
    __syncthreads();

    int cg = tid & 63, grp = tid >> 6;
    float2 acc[12];
#pragma unroll
    for (int rr = 0; rr < 12; rr++) { acc[rr].x = 0.0f; acc[rr].y = 0.0f; }
    const float2* z2 = (const float2*)zs;
    for (int l = 0; l < LF; l++) {
        float2 zv = z2[l * 64 + cg];
#pragma unroll
        for (int rr = 0; rr < 12; rr++) {
            float w = wgS[(grp * 12 + rr) * LF + l];
            acc[rr].x = fmaf(w, zv.x, acc[rr].x);
            acc[rr].y = fmaf(w, zv.y, acc[rr].y);
        }
    }
    float* mp = msg + (size_t)e * (NYR * MSGW);
#pragma unroll
    for (int rr = 0; rr < 12; rr++) {
        int row = grp * 12 + rr;
        float2 o; o.x = rtf(acc[rr].x); o.y = rtf(acc[rr].y);
        ((float2*)(mp + row * 128))[cg] = o;
    }
}

__global__ __launch_bounds__(256)
void k_out(const float* __restrict__ m2, const float* __restrict__ winv,
           float* __restrict__ out)
{
    int e = blockIdx.x, tid = threadIdx.x;
    __shared__ float mmS[16 * 128];
    __shared__ float wvS[LF * 16];
    const float4* mp4 = (const float4*)(m2 + (size_t)e * (NYR * MSGW));
    float4* mm4 = (float4*)mmS;
    for (int i4 = tid; i4 < 512; i4 += 256) {
        float4 a = mp4[i4], b = mp4[i4 + 512], c = mp4[i4 + 1024];
        float4 v;
        v.x = (a.x + b.x + c.x) * (1.0f / 3.0f);
        v.y = (a.y + b.y + c.y) * (1.0f / 3.0f);
        v.z = (a.z + b.z + c.z) * (1.0f / 3.0f);
        v.w = (a.w + b.w + c.w) * (1.0f / 3.0f);
        mm4[i4] = v;
    }
    const float4* wp4 = (const float4*)(winv + (size_t)e * (LF * 16));
    float4* wv4 = (float4*)wvS;
    for (int i4 = tid; i4 < 196; i4 += 256) wv4[i4] = wp4[i4];
    __syncthreads();

    const float INV3 = 0.5773502691896258f;
    int cg = tid & 63, grp = tid >> 6;
    const float2* mm2 = (const float2*)mmS;
    float* op = out + (size_t)e * XLC;
    for (int b = grp; b < LF; b += 4) {
        float2 s; s.x = 0.0f; s.y = 0.0f;
#pragma unroll
        for (int r = 0; r < 16; r++) {
            float w = wvS[b * 16 + r];
            float2 mv = mm2[r * 64 + cg];
            s.x = fmaf(w, mv.x, s.x);
            s.y = fmaf(w, mv.y, s.y);
        }
        s.x *= INV3; s.y *= INV3;
        ((float2*)(op + b * 128))[cg] = s;
    }
}

// ---------------------------------------------------------------------------
extern "C" void kernel_launch(void* const* d_in, const int* in_sizes, int n_in,
                              void* d_out, int out_size)
{
    const float* x      = (const float*)d_in[0];
    const float* glovec = (const float*)d_in[2];
    const float* x_edge = (const float*)d_in[3];
    const int*   eidx   = (const int*)  d_in[4];
    const float* W_cg1  = (const float*)d_in[8];
    const float* W_cg21 = (const float*)d_in[9];
    const float* W_cg22 = (const float*)d_in[10];
    const float* Wn1a   = (const float*)d_in[11];
    const float* bn1a   = (const float*)d_in[12];
    const float* Wn1b   = (const float*)d_in[13];
    const float* bn1b   = (const float*)d_in[14];
    const float* Wn2a   = (const float*)d_in[15];
    const float* bn2a   = (const float*)d_in[16];
    const float* Wn2b   = (const float*)d_in[17];
    const float* bn2b   = (const float*)d_in[18];
    const float* Wd     = (const float*)d_in[19];
    const float* bd     = (const float*)d_in[20];
    const float* Wp1    = (const float*)d_in[21];
    const float* bp1    = (const float*)d_in[22];
    const float* Wp2    = (const float*)d_in[23];
    const float* bp2    = (const float*)d_in[24];
    const float* wigner = (const float*)d_in[25];
    const float* winv   = (const float*)d_in[26];
    const float* wign   = (const float*)d_in[27];
    float* out = (float*)d_out;

    float *pWdT, *pW1aT, *pW1bT, *pW2aT, *pW2bT, *pWp1T, *pWp2T, *pWc1T, *pWc2T, *pWc3T;
    float *p_xer, *p_xe, *p_nm, *p_t3, *p_A, *p_feat, *p_h, *p_h2,
          *p_msg, *p_m1, *p_m2, *p_part;
    cudaGetSymbolAddress((void**)&pWdT,  g_WdT);
    cudaGetSymbolAddress((void**)&pW1aT, g_Wn1aT);
    cudaGetSymbolAddress((void**)&pW1bT, g_Wn1bT);
    cudaGetSymbolAddress((void**)&pW2aT, g_Wn2aT);
    cudaGetSymbolAddress((void**)&pW2bT, g_Wn2bT);
    cudaGetSymbolAddress((void**)&pWp1T, g_Wp1T);
    cudaGetSymbolAddress((void**)&pWp2T, g_Wp2T);
    cudaGetSymbolAddress((void**)&pWc1T, g_Wc1T);
    cudaGetSymbolAddress((void**)&pWc2T, g_Wc2T);
    cudaGetSymbolAddress((void**)&pWc3T, g_Wc3T);
    cudaGetSymbolAddress((void**)&p_xer,  g_xer);
    cudaGetSymbolAddress((void**)&p_xe,   g_xe);
    cudaGetSymbolAddress((void**)&p_nm,   g_nm);
    cudaGetSymbolAddress((void**)&p_t3,   g_t3);
    cudaGetSymbolAddress((void**)&p_A,    g_A);
    cudaGetSymbolAddress((void**)&p_feat, g_feat);
    cudaGetSymbolAddress((void**)&p_h,    g_h);
    cudaGetSymbolAddress((void**)&p_h2,   g_h2);
    cudaGetSymbolAddress((void**)&p_msg,  g_msg);
    cudaGetSymbolAddress((void**)&p_m1,   g_m1);
    cudaGetSymbolAddress((void**)&p_m2,   g_m2);
    cudaGetSymbolAddress((void**)&p_part, g_part);

    cudaFuncSetAttribute(tgemm, cudaFuncAttributeMaxDynamicSharedMemorySize, DYN_SMEM);

    const int BIG = 1 << 30;

    // ---- L1: weight transposes + x_edge round, ONE launch ----
    {
        TDPack P;
        auto set = [&](int i, const float* s, float* dst, int R, int C, int ldD, int& off) {
            int tx = (C + 31) / 32;
            int rows = (ldD == 0) ? R : ldD;
            int ty = (rows + 31) / 32;
            P.d[i] = TD{ s, dst, R, C, ldD, tx, off };
            off += tx * ty;
        };
        int off = 0;
        set(0, Wd,    pWdT,  128,  128,  128,  off);
        set(1, Wn1a,  pW1aT, FEATW,128,  FEATW,off);
        set(2, Wn1b,  pW1bT, 128,  2048, 128,  off);
        set(3, Wn2a,  pW2aT, FEATW,128,  FEATW,off);
        set(4, Wn2b,  pW2bT, 128,  2048, 128,  off);
        set(5, Wp1,   pWp1T, 2048, 128,  2048, off);
        set(6, Wp2,   pWp2T, 128,  2048, 128,  off);
        set(7, W_cg1, pWc1T, 49,   1225, KCG,  off);
        set(8, W_cg21,pWc2T, 49,   1225, KCG,  off);
        set(9, W_cg22,pWc3T, 49,   1225, KCG,  off);
        set(10, x_edge, p_xer, NEDGE, 128, 0,  off);   // copy-round
        k_tmulti<<<off, 256>>>(P, 11);
    }

    // ---- L2: feat (8192 blocks) + nodemean (2048 blocks) ----
    k_featnm<<<2 * NEDGE + NNODE, 128>>>(x, glovec, wign, eidx, p_feat, p_nm);

    // ---- L3: CGx3 + XE + aG split-4 in ONE tgemm launch ----
    {
        GPack P;
        // jobs 0-2: CG bilinears [4096,1225] = nm[eidx] @ WcT, K=64
        const float* wcs[3] = { pWc1T, pWc2T, pWc3T };
        for (int zi = 0; zi < 3; zi++) {
            P.j[zi] = GJob{ p_nm, wcs[zi], wcs[zi], nullptr, nullptr,
                            (zi == 2) ? (eidx + NEDGE) : eidx,
                            p_t3 + (size_t)zi * NEDGE * TPAD,
                            NEDGE, 1225, KCG, TPAD, 0, 2, BIG, 0 };
        }
        // job 3: xe GEMM [4096,128] = xer @ WdT, K=128, bias+silu
        P.j[3] = GJob{ p_xer, pWdT, pWdT, bd, bd, nullptr, p_xe,
                       NEDGE, 128, 128, 128, 0, 4, BIG, 1 };
        // jobs 4-7: feat-a GEMM split-K (chunks 65 -> 17/17/17/14), dual-B
        for (int zi = 0; zi < 4; zi++) {
            int c0 = zi * 17;
            int ce = (c0 + 17 < 65) ? c0 + 17 : 65;
            P.j[4 + zi] = GJob{ p_feat, pW1aT, pW2aT, nullptr, nullptr, nullptr,
                                p_part + (size_t)zi * 2 * NEDGE * 128,
                                2 * NEDGE, 128, FEATW, 128, c0, ce, 32, 0 };
        }
        tgemm<<<dim3(10, 64, 8), 128, DYN_SMEM>>>(P);
    }

    // ---- L4: combine<1> + midcon merged ----
    k_combmid<<<8192, 256>>>(p_part, bn1a, bn2a, p_h, p_nm, eidx,
                             p_t3, p_t3 + (size_t)NEDGE * TPAD,
                             p_t3 + 2 * (size_t)NEDGE * TPAD, p_A);

    // ---- L5: b-stage GEMM [8192,2048], dual-B, bias+silu ----
    {
        GPack P;
        P.j[0] = GJob{ p_h, pW1bT, pW2bT, bn1b, bn2b, nullptr, p_h2,
                       2 * NEDGE, 2048, 128, 2048, 0, 4, 32, 1 };
        tgemm<<<dim3(16, 64, 1), 128, DYN_SMEM>>>(P);
    }

    // ---- L6: fused sh + z-build + rotate ----
    k_rotmsg<<<NEDGE, 256>>>(x, eidx, p_A, p_h2, wign, wigner, p_msg);

    // ---- L7: Wp1 GEMM split-2 ----
    {
        GPack P;
        for (int zi = 0; zi < 2; zi++) {
            P.j[zi] = GJob{ p_msg, pWp1T, pWp1T, nullptr, nullptr, nullptr,
                            p_part + (size_t)zi * NEDGE * NYR * 128,
                            NEDGE * NYR, 128, 2048, 128, zi * 32, zi * 32 + 32, BIG, 0 };
        }
        tgemm<<<dim3(1, 96, 2), 128, DYN_SMEM>>>(P);
    }
    k_combine2<<<(NEDGE * NYR * 128 + 255) / 256, 256>>>(p_part, bp1, p_xe, p_m1,
                                                         NEDGE * NYR);

    // ---- L9: Wp2 GEMM ----
    {
        GPack P;
        P.j[0] = GJob{ p_m1, pWp2T, pWp2T, bp2, bp2, nullptr, p_m2,
                       NEDGE * NYR, 2048, 128, 2048, 0, 4, BIG, 1 };
        tgemm<<<dim3(16, 96, 1), 128, DYN_SMEM>>>(P);
    }

    // ---- L10: NY-mean + inverse rotation ----
    k_out<<<NEDGE, 256>>>(p_m2, winv, out);
}

// round 15
// speedup vs baseline: 1.0234x; 1.0234x over previous
#include <cuda_runtime.h>
#include <cstdint>
#include <math.h>

// ---------------- problem constants ----------------
#define NNODE 2048
#define NEDGE 4096
#define LF    49
#define LR    16
#define MMID  25
#define NYR   3
#define CCH   128
#define HID   128
#define XLC   (LF*CCH)      // 6272
#define FEATW 2064          // 16*129
#define MSGW  2048          // 16*128
#define TPAD  1280          // padded 1225
#define KCG   64            // padded 49

// ---------------- device scratch ----------------
__device__ __align__(16) float g_WdT  [128*128];
__device__ __align__(16) float g_Wn1aT[128*FEATW];
__device__ __align__(16) float g_Wn1bT[2048*128];
__device__ __align__(16) float g_Wn2aT[128*FEATW];
__device__ __align__(16) float g_Wn2bT[2048*128];
__device__ __align__(16) float g_Wp1T [128*2048];
__device__ __align__(16) float g_Wp2T [2048*128];
__device__ __align__(16) float g_Wc1T [TPAD*KCG];
__device__ __align__(16) float g_Wc2T [TPAD*KCG];
__device__ __align__(16) float g_Wc3T [TPAD*KCG];
__device__ __align__(16) float g_xer  [NEDGE*128];
__device__ __align__(16) float g_xe   [NEDGE*HID];
__device__ __align__(16) float g_nm   [NNODE*KCG];
__device__ __align__(16) float g_xm   [NEDGE*KCG];
__device__ __align__(16) float g_ym   [NEDGE*KCG];
__device__ __align__(16) float g_t3   [3*NEDGE*TPAD];
__device__ __align__(16) float g_A    [NEDGE*LF];
__device__ __align__(16) float g_feat [2*NEDGE*FEATW];
__device__ __align__(16) float g_h    [2*NEDGE*HID];
__device__ __align__(16) float g_h2   [2*NEDGE*MSGW];
__device__ __align__(16) float g_msg  [NEDGE*NYR*MSGW];
__device__ __align__(16) float g_m1   [NEDGE*NYR*HID];
__device__ __align__(16) float g_m2   [NEDGE*NYR*MSGW];
__device__ __align__(16) float g_part [4*12288*128];

__device__ __forceinline__ float silu_f(float v) { return v / (1.0f + __expf(-v)); }

// round fp32 -> nearest tf32 value (kept in fp32 container)
__device__ __forceinline__ float rtf(float f) {
    uint32_t r;
    asm("cvt.rna.tf32.f32 %0, %1;" : "=r"(r) : "f"(f));
    return __uint_as_float(r);
}

__device__ __forceinline__ void mma8(float* d, uint32_t a0, uint32_t a1, uint32_t a2,
                                     uint32_t a3, uint32_t b0, uint32_t b1) {
    asm volatile(
        "mma.sync.aligned.m16n8k8.row.col.f32.tf32.tf32.f32 "
        "{%0,%1,%2,%3}, {%4,%5,%6,%7}, {%8,%9}, {%0,%1,%2,%3};"
        : "+f"(d[0]), "+f"(d[1]), "+f"(d[2]), "+f"(d[3])
        : "r"(a0), "r"(a1), "r"(a2), "r"(a3), "r"(b0), "r"(b1));
}

__device__ __forceinline__ void cp16(uint32_t dst, const float* src, bool pred) {
    int sz = pred ? 16 : 0;
    asm volatile("cp.async.cg.shared.global [%0], [%1], 16, %2;"
                 :: "r"(dst), "l"(src), "r"(sz) : "memory");
}
#define CP_COMMIT() asm volatile("cp.async.commit_group;" ::: "memory")
template<int N> __device__ __forceinline__ void cpwait() {
    asm volatile("cp.async.wait_group %0;" :: "n"(N) : "memory");
}

// ---------------------------------------------------------------------------
// tf32 mma.sync GEMM (best-known R11 config): 128 threads, 2x2 warps, warp
// tile 64x64, CTA 128x128, K-chunks 32, TWO-stage cp.async double buffer,
// kk-pipelined fragment loads. Inputs MUST be tf32-pre-rounded.
// zmode=0: grid.z = split-K (C + z*M*ldc); dual-B keyed on blockIdx.y/ysplit.
// zmode=1: grid.z = batch (A/B by z).
// EPI: 0=raw, 1=bias+silu, 2=bias+silu then *= xe[(row/3)*128+col]
// ---------------------------------------------------------------------------
#define LDA 36
#define ATILE (128*LDA)
#define BUFSZ (2*ATILE)
#define DYN_SMEM (2*BUFSZ*4)     // 73728 bytes per CTA; occ 2

template<int EPI>
__global__ __launch_bounds__(128, 2)
void tgemm(const float* __restrict__ A0, const float* __restrict__ A1,
           const float* __restrict__ A2,
           const float* __restrict__ B0, const float* __restrict__ B1,
           const float* __restrict__ B2,
           const float* __restrict__ bias0, const float* __restrict__ bias1,
           const float* __restrict__ xe,
           float* __restrict__ C, int M, int Nreal, int K, int ldc,
           int chunksTotal, int chunksPerZ, int zmode, int ysplit)
{
    extern __shared__ uint32_t sm[];
    const uint32_t smBase = (uint32_t)__cvta_generic_to_shared(sm);
    const int tid  = threadIdx.x;
    const int lane = tid & 31;
    const int warp = tid >> 5;           // 0..3
    const int wm = warp >> 1, wn = warp & 1;
    const int g = lane >> 2, t = lane & 3;

    const int bm0 = blockIdx.y * 128;
    const int bn0 = blockIdx.x * 128;
    const int z   = blockIdx.z;

    const float* A;
    const float* BT;
    const float* bias;
    int c0, cend;
    if (zmode) {
        A    = (z == 0) ? A0 : (z == 1) ? A1 : A2;
        BT   = (z == 0) ? B0 : (z == 1) ? B1 : B2;
        bias = bias0;
        c0 = 0; cend = chunksTotal;
    } else {
        A    = A0;
        BT   = ((int)blockIdx.y < ysplit) ? B0 : B1;
        bias = ((int)blockIdx.y < ysplit) ? bias0 : bias1;
        c0 = z * chunksPerZ;
        cend = c0 + chunksPerZ; if (cend > chunksTotal) cend = chunksTotal;
    }

    float acc[4][8][4];                  // warp tile 64x64
#pragma unroll
    for (int i = 0; i < 4; i++)
#pragma unroll
        for (int j = 0; j < 8; j++)
#pragma unroll
            for (int q = 0; q < 4; q++) acc[i][j][q] = 0.0f;

    const int lseg = tid & 7;

    auto issue = [&](int c, int b) {
        const int kbase = c * 32;
        const int gk = kbase + lseg * 4;
        const bool kok = gk < K;
        uint32_t As = smBase + (uint32_t)(b * BUFSZ) * 4;
        uint32_t Bs = As + ATILE * 4;
#pragma unroll
        for (int i = 0; i < 8; i++) {
            int idx = tid + i * 128;
            int r = idx >> 3;
            cp16(As + (uint32_t)(r * LDA + lseg * 4) * 4,
                 A + (size_t)(bm0 + r) * K + gk, kok);
        }
#pragma unroll
        for (int i = 0; i < 8; i++) {
            int idx = tid + i * 128;
            int r = idx >> 3;
            int gn = bn0 + r;
            cp16(Bs + (uint32_t)(r * LDA + lseg * 4) * 4,
                 BT + (size_t)gn * K + gk, kok && (gn < Nreal));
        }
        CP_COMMIT();
    };

    issue(c0, 0);
    for (int c = c0; c < cend; ++c) {
        int b = (c - c0) & 1;
        if (c + 1 < cend) { issue(c + 1, b ^ 1); cpwait<1>(); }
        else              { cpwait<0>(); }
        __syncthreads();

        const uint32_t* As = sm + b * BUFSZ;
        const uint32_t* Bs = As + ATILE;

        uint32_t af[2][4][4], bf[2][8][2];
        auto loadfrag = [&](int kk, int buf) {
            const int k0 = kk * 8;
#pragma unroll
            for (int i = 0; i < 4; i++) {
                int mb = wm * 64 + i * 16;
                af[buf][i][0] = As[(mb + g)     * LDA + k0 + t];
                af[buf][i][1] = As[(mb + g + 8) * LDA + k0 + t];
                af[buf][i][2] = As[(mb + g)     * LDA + k0 + t + 4];
                af[buf][i][3] = As[(mb + g + 8) * LDA + k0 + t + 4];
            }
#pragma unroll
            for (int j = 0; j < 8; j++) {
                int nb = wn * 64 + j * 8;
                bf[buf][j][0] = Bs[(nb + g) * LDA + k0 + t];
                bf[buf][j][1] = Bs[(nb + g) * LDA + k0 + t + 4];
            }
        };

        loadfrag(0, 0);
#pragma unroll
        for (int kk = 0; kk < 4; kk++) {
            int cur = kk & 1;
            if (kk < 3) loadfrag(kk + 1, cur ^ 1);
#pragma unroll
            for (int i = 0; i < 4; i++)
#pragma unroll
                for (int j = 0; j < 8; j++)
                    mma8(acc[i][j], af[cur][i][0], af[cur][i][1],
                         af[cur][i][2], af[cur][i][3],
                         bf[cur][j][0], bf[cur][j][1]);
        }
        __syncthreads();   // all warps done reading buf b before refill (c+2)
    }

    float* Cz = C + (size_t)z * M * ldc;
#pragma unroll
    for (int i = 0; i < 4; i++) {
        int r0 = bm0 + wm * 64 + i * 16 + g;
#pragma unroll
        for (int j = 0; j < 8; j++) {
            int cc = bn0 + wn * 64 + j * 8 + 2 * t;
#pragma unroll
            for (int half = 0; half < 2; half++) {
                int row = r0 + half * 8;
                float v0 = acc[i][j][half * 2 + 0];
                float v1 = acc[i][j][half * 2 + 1];
                if (cc < Nreal) {
                    if (EPI >= 1) {
                        v0 = silu_f(v0 + bias[cc]);
                        v1 = (cc + 1 < Nreal) ? silu_f(v1 + bias[cc + 1]) : 0.0f;
                    }
                    if (EPI == 2) {
                        const float* xr = xe + (size_t)(row / 3) * 128;
                        v0 *= xr[cc];
                        if (cc + 1 < Nreal) v1 *= xr[cc + 1];
                    }
                    float* cp = Cz + (size_t)row * ldc + cc;
                    if (cc + 1 < Nreal) { float2 fv = make_float2(v0, v1); *(float2*)cp = fv; }
                    else cp[0] = v0;
                }
            }
        }
    }
}

// combine split-K partials (float4-vectorized): out = epi(sum_z part[z]+bias)
// grid covers M*128/4 float4 elements. bias1 used for rows >= Mhalf.
template<int EPI>
__global__ void k_combine(const float* __restrict__ part, const float* __restrict__ bias0,
                          const float* __restrict__ bias1, const float* __restrict__ xe,
                          float* __restrict__ outp, int M, int nsplit, int Mhalf)
{
    int i4 = blockIdx.x * 256 + threadIdx.x;
    if (i4 >= M * 32) return;
    int m = i4 >> 5, n4 = (i4 & 31) * 4;
    const float* bias = (m < Mhalf) ? bias0 : bias1;
    float4 s = *(const float4*)(bias + n4);
    for (int zz = 0; zz < nsplit; zz++) {
        float4 p = *(const float4*)(part + (size_t)zz * M * 128 + (size_t)i4 * 4);
        s.x += p.x; s.y += p.y; s.z += p.z; s.w += p.w;
    }
    s.x = silu_f(s.x); s.y = silu_f(s.y); s.z = silu_f(s.z); s.w = silu_f(s.w);
    if (EPI == 2) {
        const float4 xr = *(const float4*)(xe + (size_t)(m / 3) * 128 + n4);
        s.x *= xr.x; s.y *= xr.y; s.z *= xr.z; s.w *= xr.w;
    }
    float4 o;
    o.x = rtf(s.x); o.y = rtf(s.y); o.z = rtf(s.z); o.w = rtf(s.w);
    *(float4*)(outp + (size_t)i4 * 4) = o;
}

// tf32-round a buffer
__global__ void k_round(const float* __restrict__ src, float* __restrict__ dst, int n)
{
    int i = blockIdx.x * 256 + threadIdx.x;
    if (i < n) dst[i] = rtf(src[i]);
}

// ---------------- fused multi-transpose (tf32-rounded output) ----------------
struct TD { const float* src; float* dst; int R, C, ldD, tilesX, tileOff; };
struct TDPack { TD d[10]; };

__global__ void k_tmulti(TDPack P, int ndesc)
{
    __shared__ float smt[32][33];
    int bid = blockIdx.x;
    int di = 0;
    for (int i = 1; i < ndesc; i++) if (bid >= P.d[i].tileOff) di = i;
    const TD& D = P.d[di];
    int ti = bid - D.tileOff;
    int c0 = (ti % D.tilesX) * 32;
    int r0 = (ti / D.tilesX) * 32;
    int tx = threadIdx.x & 31, ty = threadIdx.x >> 5;
#pragma unroll
    for (int i = 0; i < 4; i++) {
        int r = r0 + ty + i * 8, c = c0 + tx;
        smt[ty + i * 8][tx] = (r < D.R && c < D.C) ? rtf(D.src[(size_t)r * D.C + c]) : 0.0f;
    }
    __syncthreads();
#pragma unroll
    for (int i = 0; i < 4; i++) {
        int c = c0 + ty + i * 8, r = r0 + tx;
        if (c < D.C && r < D.ldD) D.dst[(size_t)c * D.ldD + r] = smt[tx][ty + i * 8];
    }
}

// ---------------------------------------------------------------------------
// per-edge kernels
// ---------------------------------------------------------------------------
__global__ void k_nodemean(const float* __restrict__ x, float* __restrict__ nm)
{
    int n = blockIdx.x, tid = threadIdx.x;
    int lane = tid & 31, warp = tid >> 5;
    const float4* p = (const float4*)(x + (size_t)n * XLC);
    if (tid >= 49 && tid < 64) nm[n * KCG + tid] = 0.f;
    for (int l = warp; l < LF; l += 4) {
        float4 a = p[l * 32 + lane];
        float s = (a.x + a.y) + (a.z + a.w);
#pragma unroll
        for (int o = 16; o > 0; o >>= 1)
            s += __shfl_xor_sync(0xffffffffu, s, o);
        if (lane == 0) nm[n * KCG + l] = rtf(s * (1.0f / 128.0f));
    }
}

// gather node means to edges (float4: 16 float4 per edge row)
__global__ void k_gather(const float* __restrict__ nm, const int* __restrict__ eidx,
                         float* __restrict__ xm, float* __restrict__ ym)
{
    int i4 = blockIdx.x * 256 + threadIdx.x;
    if (i4 >= NEDGE * 16) return;
    int e = i4 >> 4, tt = i4 & 15;
    const float4* nm4 = (const float4*)nm;
    ((float4*)xm)[i4] = nm4[eidx[e] * 16 + tt];
    ((float4*)ym)[i4] = nm4[eidx[NEDGE + e] * 16 + tt];
}

// merged: mid[o] = sum_j ym[j]*t1[j*25+o]; A[o] = sum_j mid[j]*(t2+t3)[j*49+o]
__global__ void k_midcon(const float* __restrict__ ym, const float* __restrict__ t1,
                         const float* __restrict__ t2, const float* __restrict__ t3,
                         float* __restrict__ Aout)
{
    int e = blockIdx.x, tid = threadIdx.x;   // 64 threads
    __shared__ float ys[LF];
    __shared__ float ms[MMID];
    if (tid < LF) ys[tid] = ym[e * KCG + tid];
    __syncthreads();
    if (tid < MMID) {
        const float* tp = t1 + (size_t)e * TPAD + tid;
        float s = 0.0f;
#pragma unroll
        for (int j = 0; j < LF; j++) s = fmaf(ys[j], tp[j * MMID], s);
        ms[tid] = s;
    }
    __syncthreads();
    if (tid < LF) {
        const float* tp2 = t2 + (size_t)e * TPAD + tid;
        const float* tp3 = t3 + (size_t)e * TPAD + tid;
        float s = 0.0f;
#pragma unroll
        for (int j = 0; j < MMID; j++)
            s = fmaf(ms[j], tp2[j * LF] + tp3[j * LF], s);
        Aout[e * LF + tid] = s;
    }
}

// batched: blocks 0..4095 -> (node=src, other=dst); 4096..8191 -> swapped
__global__ void k_feat(const float* __restrict__ x, const float* __restrict__ glovec,
                       const float* __restrict__ wign, const int* __restrict__ eidx,
                       float* __restrict__ feat)
{
    int e2 = blockIdx.x, tid = threadIdx.x;
    int half = e2 >> 12;
    int e = e2 & 4095;
    __shared__ float wigS[256];
    __shared__ float gS[16];
    __shared__ float red[64];
    int node  = eidx[half ? (NEDGE + e) : e];
    int other = eidx[half ? e : (NEDGE + e)];
    wigS[tid]       = wign[e * 256 + tid];
    wigS[tid + 128] = wign[e * 256 + 128 + tid];
    if (tid < 16) gS[tid] = glovec[other * LR + tid];
    __syncthreads();

    float xr[16];
    const float* xp = x + (size_t)node * XLC;
#pragma unroll
    for (int j = 0; j < 16; j++) xr[j] = xp[j * 128 + tid];

    int lane = tid & 31, warp = tid >> 5;
    float* fp = feat + (size_t)e2 * FEATW;
#pragma unroll
    for (int i = 0; i < 16; i++) {
        float a = 0.0f;
#pragma unroll
        for (int j = 0; j < 16; j++) a = fmaf(wigS[j * 16 + i], xr[j], a);
        fp[i * 129 + tid] = rtf(a);
        float s = a;
#pragma unroll
        for (int o = 16; o > 0; o >>= 1) s += __shfl_xor_sync(0xffffffffu, s, o);
        if (lane == 0) red[i * 4 + warp] = s;
    }
    __syncthreads();
    if (tid < 16) {
        float s = red[tid * 4] + red[tid * 4 + 1] + red[tid * 4 + 2] + red[tid * 4 + 3];
        fp[tid * 129 + 128] = rtf(s * (1.0f / 128.0f) * gS[tid]);
    }
}

// fused: sh compute (wig_node @ (h2a+h2b)) + z-build + wigner rotate
__global__ __launch_bounds__(256)
void k_rotmsg(const float* __restrict__ x, const int* __restrict__ eidx,
              const float* __restrict__ Aarr, const float* __restrict__ h2,
              const float* __restrict__ wign, const float* __restrict__ wigner,
              float* __restrict__ msg)
{
    int e = blockIdx.x, tid = threadIdx.x;
    __shared__ float zs[LF * 128];
    __shared__ float wgS[48 * 49];
    __shared__ float As_[LF];
    __shared__ float wigS[256];
    int src = eidx[e], dst = eidx[NEDGE + e];
    const float4* xs4 = (const float4*)(x + (size_t)src * XLC);
    const float4* xt4 = (const float4*)(x + (size_t)dst * XLC);
    wigS[tid] = wign[e * 256 + tid];
    if (tid < LF) As_[tid] = Aarr[e * LF + tid];
    __syncthreads();

    float4* zs4 = (float4*)zs;
    for (int i4 = tid; i4 < LF * 32; i4 += 256) {
        int l = i4 >> 5;
        float4 a = xs4[i4], b = xt4[i4];
        float al = As_[l];
        float4 v;
        v.x = 2.0f * (a.x + b.x) + al;
        v.y = 2.0f * (a.y + b.y) + al;
        v.z = 2.0f * (a.z + b.z) + al;
        v.w = 2.0f * (a.w + b.w) + al;
        zs4[i4] = v;
    }
    const float4* wp4 = (const float4*)(wigner + (size_t)e * (48 * 49));
    float4* wg4 = (float4*)wgS;
    for (int i4 = tid; i4 < 588; i4 += 256) wg4[i4] = wp4[i4];
    __syncthreads();

    if (tid < 128) {
        float hr[16];
        const float* hpa = h2 + (size_t)e * MSGW;
        const float* hpb = h2 + (size_t)(e + NEDGE) * MSGW;
#pragma unroll
        for (int j = 0; j < 16; j++) hr[j] = hpa[j * 128 + tid] + hpb[j * 128 + tid];
#pragma unroll
        for (int i = 0; i < 16; i++) {
            float s = 0.0f;
#pragma unroll
            for (int j = 0; j < 16; j++) s = fmaf(wigS[i * 16 + j], hr[j], s);
            zs[i * 128 + tid] += s;
        }
    }
    __syncthreads();

    int cg = tid & 63, grp = tid >> 6;
    float2 acc[12];
#pragma unroll
    for (int rr = 0; rr < 12; rr++) { acc[rr].x = 0.0f; acc[rr].y = 0.0f; }
    const float2* z2 = (const float2*)zs;
    for (int l = 0; l < LF; l++) {
        float2 zv = z2[l * 64 + cg];
#pragma unroll
        for (int rr = 0; rr < 12; rr++) {
            float w = wgS[(grp * 12 + rr) * LF + l];
            acc[rr].x = fmaf(w, zv.x, acc[rr].x);
            acc[rr].y = fmaf(w, zv.y, acc[rr].y);
        }
    }
    float* mp = msg + (size_t)e * (NYR * MSGW);
#pragma unroll
    for (int rr = 0; rr < 12; rr++) {
        int row = grp * 12 + rr;
        float2 o; o.x = rtf(acc[rr].x); o.y = rtf(acc[rr].y);
        ((float2*)(mp + row * 128))[cg] = o;
    }
}

__global__ __launch_bounds__(256)
void k_out(const float* __restrict__ m2, const float* __restrict__ winv,
           float* __restrict__ out)
{
    int e = blockIdx.x, tid = threadIdx.x;
    __shared__ float mmS[16 * 128];
    __shared__ float wvS[LF * 16];
    const float4* mp4 = (const float4*)(m2 + (size_t)e * (NYR * MSGW));
    float4* mm4 = (float4*)mmS;
    for (int i4 = tid; i4 < 512; i4 += 256) {
        float4 a = mp4[i4], b = mp4[i4 + 512], c = mp4[i4 + 1024];
        float4 v;
        v.x = (a.x + b.x + c.x) * (1.0f / 3.0f);
        v.y = (a.y + b.y + c.y) * (1.0f / 3.0f);
        v.z = (a.z + b.z + c.z) * (1.0f / 3.0f);
        v.w = (a.w + b.w + c.w) * (1.0f / 3.0f);
        mm4[i4] = v;
    }
    const float4* wp4 = (const float4*)(winv + (size_t)e * (LF * 16));
    float4* wv4 = (float4*)wvS;
    for (int i4 = tid; i4 < 196; i4 += 256) wv4[i4] = wp4[i4];
    __syncthreads();

    const float INV3 = 0.5773502691896258f;
    int cg = tid & 63, grp = tid >> 6;
    const float2* mm2 = (const float2*)mmS;
    float* op = out + (size_t)e * XLC;
    for (int b = grp; b < LF; b += 4) {
        float2 s; s.x = 0.0f; s.y = 0.0f;
#pragma unroll
        for (int r = 0; r < 16; r++) {
            float w = wvS[b * 16 + r];
            float2 mv = mm2[r * 64 + cg];
            s.x = fmaf(w, mv.x, s.x);
            s.y = fmaf(w, mv.y, s.y);
        }
        s.x *= INV3; s.y *= INV3;
        ((float2*)(op + b * 128))[cg] = s;
    }
}

// ---------------------------------------------------------------------------
extern "C" void kernel_launch(void* const* d_in, const int* in_sizes, int n_in,
                              void* d_out, int out_size)
{
    const float* x      = (const float*)d_in[0];
    const float* glovec = (const float*)d_in[2];
    const float* x_edge = (const float*)d_in[3];
    const int*   eidx   = (const int*)  d_in[4];
    const float* W_cg1  = (const float*)d_in[8];
    const float* W_cg21 = (const float*)d_in[9];
    const float* W_cg22 = (const float*)d_in[10];
    const float* Wn1a   = (const float*)d_in[11];
    const float* bn1a   = (const float*)d_in[12];
    const float* Wn1b   = (const float*)d_in[13];
    const float* bn1b   = (const float*)d_in[14];
    const float* Wn2a   = (const float*)d_in[15];
    const float* bn2a   = (const float*)d_in[16];
    const float* Wn2b   = (const float*)d_in[17];
    const float* bn2b   = (const float*)d_in[18];
    const float* Wd     = (const float*)d_in[19];
    const float* bd     = (const float*)d_in[20];
    const float* Wp1    = (const float*)d_in[21];
    const float* bp1    = (const float*)d_in[22];
    const float* Wp2    = (const float*)d_in[23];
    const float* bp2    = (const float*)d_in[24];
    const float* wigner = (const float*)d_in[25];
    const float* winv   = (const float*)d_in[26];
    const float* wign   = (const float*)d_in[27];
    float* out = (float*)d_out;

    float *pWdT, *pW1aT, *pW1bT, *pW2aT, *pW2bT, *pWp1T, *pWp2T, *pWc1T, *pWc2T, *pWc3T;
    float *p_xer, *p_xe, *p_nm, *p_xm, *p_ym, *p_t3, *p_A, *p_feat, *p_h, *p_h2,
          *p_msg, *p_m1, *p_m2, *p_part;
    cudaGetSymbolAddress((void**)&pWdT,  g_WdT);
    cudaGetSymbolAddress((void**)&pW1aT, g_Wn1aT);
    cudaGetSymbolAddress((void**)&pW1bT, g_Wn1bT);
    cudaGetSymbolAddress((void**)&pW2aT, g_Wn2aT);
    cudaGetSymbolAddress((void**)&pW2bT, g_Wn2bT);
    cudaGetSymbolAddress((void**)&pWp1T, g_Wp1T);
    cudaGetSymbolAddress((void**)&pWp2T, g_Wp2T);
    cudaGetSymbolAddress((void**)&pWc1T, g_Wc1T);
    cudaGetSymbolAddress((void**)&pWc2T, g_Wc2T);
    cudaGetSymbolAddress((void**)&pWc3T, g_Wc3T);
    cudaGetSymbolAddress((void**)&p_xer,  g_xer);
    cudaGetSymbolAddress((void**)&p_xe,   g_xe);
    cudaGetSymbolAddress((void**)&p_nm,   g_nm);
    cudaGetSymbolAddress((void**)&p_xm,   g_xm);
    cudaGetSymbolAddress((void**)&p_ym,   g_ym);
    cudaGetSymbolAddress((void**)&p_t3,   g_t3);
    cudaGetSymbolAddress((void**)&p_A,    g_A);
    cudaGetSymbolAddress((void**)&p_feat, g_feat);
    cudaGetSymbolAddress((void**)&p_h,    g_h);
    cudaGetSymbolAddress((void**)&p_h2,   g_h2);
    cudaGetSymbolAddress((void**)&p_msg,  g_msg);
    cudaGetSymbolAddress((void**)&p_m1,   g_m1);
    cudaGetSymbolAddress((void**)&p_m2,   g_m2);
    cudaGetSymbolAddress((void**)&p_part, g_part);

    cudaFuncSetAttribute(tgemm<0>, cudaFuncAttributeMaxDynamicSharedMemorySize, DYN_SMEM);
    cudaFuncSetAttribute(tgemm<1>, cudaFuncAttributeMaxDynamicSharedMemorySize, DYN_SMEM);
    cudaFuncSetAttribute(tgemm<2>, cudaFuncAttributeMaxDynamicSharedMemorySize, DYN_SMEM);

    const int BIG = 1 << 30;

    // ---- weight transposes (tf32-rounded) + x_edge rounding ----
    {
        TDPack P;
        auto set = [&](int i, const float* s, float* dst, int R, int C, int ldD, int& off) {
            int tx = (C + 31) / 32, ty = (ldD + 31) / 32;
            P.d[i] = TD{ s, dst, R, C, ldD, tx, off };
            off += tx * ty;
        };
        int off = 0;
        set(0, Wd,    pWdT,  128,  128,  128,  off);
        set(1, Wn1a,  pW1aT, FEATW,128,  FEATW,off);
        set(2, Wn1b,  pW1bT, 128,  2048, 128,  off);
        set(3, Wn2a,  pW2aT, FEATW,128,  FEATW,off);
        set(4, Wn2b,  pW2bT, 128,  2048, 128,  off);
        set(5, Wp1,   pWp1T, 2048, 128,  2048, off);
        set(6, Wp2,   pWp2T, 128,  2048, 128,  off);
        set(7, W_cg1, pWc1T, 49,   1225, KCG,  off);
        set(8, W_cg21,pWc2T, 49,   1225, KCG,  off);
        set(9, W_cg22,pWc3T, 49,   1225, KCG,  off);
        k_tmulti<<<off, 256>>>(P, 10);
    }
    k_round<<<(NEDGE * 128 + 255) / 256, 256>>>(x_edge, p_xer, NEDGE * 128);

    // 1. xe = silu(x_edge @ Wd + bd)
    tgemm<1><<<dim3(1, 32, 1), 128, DYN_SMEM>>>(
        p_xer, nullptr, nullptr, pWdT, nullptr, nullptr, bd, nullptr, nullptr,
        p_xe, NEDGE, 128, 128, 128, 4, 4, 0, BIG);

    // 2. per-node channel means, gathered to edges
    k_nodemean<<<NNODE, 128>>>(x, p_nm);
    k_gather<<<(NEDGE * 16 + 255) / 256, 256>>>(p_nm, eidx, p_xm, p_ym);

    // 3. CG bilinears: batched z=3, then fused mid+contract
    tgemm<0><<<dim3(10, 32, 3), 128, DYN_SMEM>>>(
        p_xm, p_xm, p_ym, pWc1T, pWc2T, pWc3T, nullptr, nullptr, nullptr,
        p_t3, NEDGE, 1225, KCG, TPAD, 2, 2, 1, BIG);
    k_midcon<<<NEDGE, 64>>>(p_ym, p_t3, p_t3 + (size_t)NEDGE * TPAD,
                            p_t3 + 2 * (size_t)NEDGE * TPAD, p_A);

    // 4+5. node_interactions batched
    k_feat<<<2 * NEDGE, 128>>>(x, glovec, wign, eidx, p_feat);
    tgemm<0><<<dim3(1, 64, 4), 128, DYN_SMEM>>>(
        p_feat, nullptr, nullptr, pW1aT, pW2aT, nullptr, nullptr, nullptr, nullptr,
        p_part, 2 * NEDGE, 128, FEATW, 128, 65, 17, 0, 32);
    k_combine<1><<<(2 * NEDGE * 32 + 255) / 256, 256>>>(
        p_part, bn1a, bn2a, nullptr, p_h, 2 * NEDGE, 4, NEDGE);
    tgemm<1><<<dim3(16, 64, 1), 128, DYN_SMEM>>>(
        p_h, nullptr, nullptr, pW1bT, pW2bT, nullptr, bn1b, bn2b, nullptr,
        p_h2, 2 * NEDGE, 2048, 128, 2048, 4, 4, 0, 32);

    // 6. fused sh + z-build + rotate (msg tf32-rounded for Wp1 GEMM)
    k_rotmsg<<<NEDGE, 256>>>(x, eidx, p_A, p_h2, wign, wigner, p_msg);

    // 7. edge MLP
    tgemm<0><<<dim3(1, 96, 2), 128, DYN_SMEM>>>(
        p_msg, nullptr, nullptr, pWp1T, nullptr, nullptr, nullptr, nullptr, nullptr,
        p_part, NEDGE * NYR, 128, 2048, 128, 64, 32, 0, BIG);
    k_combine<2><<<(NEDGE * NYR * 32 + 255) / 256, 256>>>(
        p_part, bp1, bp1, p_xe, p_m1, NEDGE * NYR, 2, BIG);
    tgemm<1><<<dim3(16, 96, 1), 128, DYN_SMEM>>>(
        p_m1, nullptr, nullptr, pWp2T, nullptr, nullptr, bp2, nullptr, nullptr,
        p_m2, NEDGE * NYR, 2048, 128, 2048, 4, 4, 0, BIG);

    // 8. NY-mean + inverse rotation
    k_out<<<NEDGE, 256>>>(p_m2, winv, out);
}

// round 16
// speedup vs baseline: 1.5193x; 1.4847x over previous
#include <cuda_runtime.h>
#include <cstdint>
#include <math.h>

// ---------------- problem constants ----------------
#define NNODE 2048
#define NEDGE 4096
#define LF    49
#define LR    16
#define MMID  25
#define NYR   3
#define CCH   128
#define HID   128
#define XLC   (LF*CCH)      // 6272
#define FEATW 2064          // 16*129
#define MSGW  2048          // 16*128
#define TPAD  1280          // padded 1225
#define KCG   64            // padded 49

// ---------------- device scratch ----------------
__device__ __align__(16) float g_WdT  [128*128];
__device__ __align__(16) float g_Wn1aT[128*FEATW];
__device__ __align__(16) float g_Wn1bT[2048*128];
__device__ __align__(16) float g_Wn2aT[128*FEATW];
__device__ __align__(16) float g_Wn2bT[2048*128];
__device__ __align__(16) float g_Wp1T [128*2048];
__device__ __align__(16) float g_Wp2T [2048*128];
__device__ __align__(16) float g_Wc1T [TPAD*KCG];
__device__ __align__(16) float g_Wc2T [TPAD*KCG];
__device__ __align__(16) float g_Wc3T [TPAD*KCG];
__device__ __align__(16) float g_xer  [NEDGE*128];
__device__ __align__(16) float g_xe   [NEDGE*HID];
__device__ __align__(16) float g_nm   [NNODE*KCG];
__device__ __align__(16) float g_xm   [NEDGE*KCG];
__device__ __align__(16) float g_ym   [NEDGE*KCG];
__device__ __align__(16) float g_t3   [3*NEDGE*TPAD];
__device__ __align__(16) float g_A    [NEDGE*LF];
__device__ __align__(16) float g_feat [2*NEDGE*FEATW];
__device__ __align__(16) float g_h    [2*NEDGE*HID];
__device__ __align__(16) float g_h2   [2*NEDGE*MSGW];
__device__ __align__(16) float g_msg  [NEDGE*NYR*MSGW];
__device__ __align__(16) float g_m1   [NEDGE*NYR*HID];
__device__ __align__(16) float g_m2   [NEDGE*NYR*MSGW];
__device__ __align__(16) float g_part [4*12288*128];

__device__ __forceinline__ float silu_f(float v) { return v / (1.0f + __expf(-v)); }

// round fp32 -> nearest tf32 value (kept in fp32 container)
__device__ __forceinline__ float rtf(float f) {
    uint32_t r;
    asm("cvt.rna.tf32.f32 %0, %1;" : "=r"(r) : "f"(f));
    return __uint_as_float(r);
}

__device__ __forceinline__ void mma8(float* d, uint32_t a0, uint32_t a1, uint32_t a2,
                                     uint32_t a3, uint32_t b0, uint32_t b1) {
    asm volatile(
        "mma.sync.aligned.m16n8k8.row.col.f32.tf32.tf32.f32 "
        "{%0,%1,%2,%3}, {%4,%5,%6,%7}, {%8,%9}, {%0,%1,%2,%3};"
        : "+f"(d[0]), "+f"(d[1]), "+f"(d[2]), "+f"(d[3])
        : "r"(a0), "r"(a1), "r"(a2), "r"(a3), "r"(b0), "r"(b1));
}

__device__ __forceinline__ void cp16(uint32_t dst, const float* src, bool pred) {
    int sz = pred ? 16 : 0;
    asm volatile("cp.async.cg.shared.global [%0], [%1], 16, %2;"
                 :: "r"(dst), "l"(src), "r"(sz) : "memory");
}
#define CP_COMMIT() asm volatile("cp.async.commit_group;" ::: "memory")
template<int N> __device__ __forceinline__ void cpwait() {
    asm volatile("cp.async.wait_group %0;" :: "n"(N) : "memory");
}

// ---------------------------------------------------------------------------
// tf32 mma.sync GEMM: 128 threads, 2x2 warps, warp tile 64x64, CTA 128x128,
// K-chunks 32, cp.async double buffer, kk-software-pipelined fragment loads.
// Inputs MUST be tf32-pre-rounded.
// zmode=0: grid.z = split-K (C + z*M*ldc); dual-B keyed on blockIdx.y/ysplit.
// zmode=1: grid.z = batch (A/B by z).
// EPI: 0=raw, 1=bias+silu, 2=bias+silu then *= xe[(row/3)*128+col]
// ---------------------------------------------------------------------------
#define LDA 36
#define ATILE (128*LDA)
#define BUFSZ (2*ATILE)
#define DYN_SMEM (2*BUFSZ*4)     // 73728 bytes per CTA; occ 2

template<int EPI>
__global__ __launch_bounds__(128, 2)
void tgemm(const float* __restrict__ A0, const float* __restrict__ A1,
           const float* __restrict__ A2,
           const float* __restrict__ B0, const float* __restrict__ B1,
           const float* __restrict__ B2,
           const float* __restrict__ bias0, const float* __restrict__ bias1,
           const float* __restrict__ xe,
           float* __restrict__ C, int M, int Nreal, int K, int ldc,
           int chunksTotal, int chunksPerZ, int zmode, int ysplit)
{
    extern __shared__ uint32_t sm[];
    const uint32_t smBase = (uint32_t)__cvta_generic_to_shared(sm);
    const int tid  = threadIdx.x;
    const int lane = tid & 31;
    const int warp = tid >> 5;           // 0..3
    const int wm = warp >> 1, wn = warp & 1;
    const int g = lane >> 2, t = lane & 3;

    const int bm0 = blockIdx.y * 128;
    const int bn0 = blockIdx.x * 128;
    const int z   = blockIdx.z;

    const float* A;
    const float* BT;
    const float* bias;
    int c0, cend;
    if (zmode) {
        A    = (z == 0) ? A0 : (z == 1) ? A1 : A2;
        BT   = (z == 0) ? B0 : (z == 1) ? B1 : B2;
        bias = bias0;
        c0 = 0; cend = chunksTotal;
    } else {
        A    = A0;
        BT   = ((int)blockIdx.y < ysplit) ? B0 : B1;
        bias = ((int)blockIdx.y < ysplit) ? bias0 : bias1;
        c0 = z * chunksPerZ;
        cend = c0 + chunksPerZ; if (cend > chunksTotal) cend = chunksTotal;
    }

    float acc[4][8][4];                  // warp tile 64x64
#pragma unroll
    for (int i = 0; i < 4; i++)
#pragma unroll
        for (int j = 0; j < 8; j++)
#pragma unroll
            for (int q = 0; q < 4; q++) acc[i][j][q] = 0.0f;

    const int lseg = tid & 7;

    auto issue = [&](int c, int b) {
        const int kbase = c * 32;
        const int gk = kbase + lseg * 4;
        const bool kok = gk < K;
        uint32_t As = smBase + (uint32_t)(b * BUFSZ) * 4;
        uint32_t Bs = As + ATILE * 4;
#pragma unroll
        for (int i = 0; i < 8; i++) {
            int idx = tid + i * 128;
            int r = idx >> 3;
            cp16(As + (uint32_t)(r * LDA + lseg * 4) * 4,
                 A + (size_t)(bm0 + r) * K + gk, kok);
        }
#pragma unroll
        for (int i = 0; i < 8; i++) {
            int idx = tid + i * 128;
            int r = idx >> 3;
            int gn = bn0 + r;
            cp16(Bs + (uint32_t)(r * LDA + lseg * 4) * 4,
                 BT + (size_t)gn * K + gk, kok && (gn < Nreal));
        }
        CP_COMMIT();
    };

    issue(c0, 0);
    for (int c = c0; c < cend; ++c) {
        int b = (c - c0) & 1;
        if (c + 1 < cend) { issue(c + 1, b ^ 1); cpwait<1>(); }
        else              { cpwait<0>(); }
        __syncthreads();

        const uint32_t* As = sm + b * BUFSZ;
        const uint32_t* Bs = As + ATILE;

        uint32_t af[2][4][4], bf[2][8][2];
        auto loadfrag = [&](int kk, int buf) {
            const int k0 = kk * 8;
#pragma unroll
            for (int i = 0; i < 4; i++) {
                int mb = wm * 64 + i * 16;
                af[buf][i][0] = As[(mb + g)     * LDA + k0 + t];
                af[buf][i][1] = As[(mb + g + 8) * LDA + k0 + t];
                af[buf][i][2] = As[(mb + g)     * LDA + k0 + t + 4];
                af[buf][i][3] = As[(mb + g + 8) * LDA + k0 + t + 4];
            }
#pragma unroll
            for (int j = 0; j < 8; j++) {
                int nb = wn * 64 + j * 8;
                bf[buf][j][0] = Bs[(nb + g) * LDA + k0 + t];
                bf[buf][j][1] = Bs[(nb + g) * LDA + k0 + t + 4];
            }
        };

        loadfrag(0, 0);
#pragma unroll
        for (int kk = 0; kk < 4; kk++) {
            int cur = kk & 1;
            if (kk < 3) loadfrag(kk + 1, cur ^ 1);
#pragma unroll
            for (int i = 0; i < 4; i++)
#pragma unroll
                for (int j = 0; j < 8; j++)
                    mma8(acc[i][j], af[cur][i][0], af[cur][i][1],
                         af[cur][i][2], af[cur][i][3],
                         bf[cur][j][0], bf[cur][j][1]);
        }
        __syncthreads();   // all warps done reading buf b before refill (c+2)
    }

    float* Cz = C + (size_t)z * M * ldc;
#pragma unroll
    for (int i = 0; i < 4; i++) {
        int r0 = bm0 + wm * 64 + i * 16 + g;
#pragma unroll
        for (int j = 0; j < 8; j++) {
            int cc = bn0 + wn * 64 + j * 8 + 2 * t;
#pragma unroll
            for (int half = 0; half < 2; half++) {
                int row = r0 + half * 8;
                float v0 = acc[i][j][half * 2 + 0];
                float v1 = acc[i][j][half * 2 + 1];
                if (cc < Nreal) {
                    if (EPI >= 1) {
                        v0 = silu_f(v0 + bias[cc]);
                        v1 = (cc + 1 < Nreal) ? silu_f(v1 + bias[cc + 1]) : 0.0f;
                    }
                    if (EPI == 2) {
                        const float* xr = xe + (size_t)(row / 3) * 128;
                        v0 *= xr[cc];
                        if (cc + 1 < Nreal) v1 *= xr[cc + 1];
                    }
                    float* cp = Cz + (size_t)row * ldc + cc;
                    if (cc + 1 < Nreal) { float2 fv = make_float2(v0, v1); *(float2*)cp = fv; }
                    else cp[0] = v0;
                }
            }
        }
    }
}

// combine split-K partials: out = epi(sum_z part[z] + bias), tf32-rounded.
template<int EPI>
__global__ void k_combine(const float* __restrict__ part, const float* __restrict__ bias0,
                          const float* __restrict__ bias1, const float* __restrict__ xe,
                          float* __restrict__ outp, int M, int nsplit, int Mhalf)
{
    int idx = blockIdx.x * 256 + threadIdx.x;
    if (idx >= M * 128) return;
    int m = idx >> 7, n = idx & 127;
    float s = (m < Mhalf) ? bias0[n] : bias1[n];
    for (int zz = 0; zz < nsplit; zz++) s += part[(size_t)zz * M * 128 + idx];
    s = silu_f(s);
    if (EPI == 2) s *= xe[(size_t)(m / 3) * 128 + n];
    outp[idx] = rtf(s);
}

// tf32-round a buffer
__global__ void k_round(const float* __restrict__ src, float* __restrict__ dst, int n)
{
    int i = blockIdx.x * 256 + threadIdx.x;
    if (i < n) dst[i] = rtf(src[i]);
}

// ---------------- fused multi-transpose (tf32-rounded output) ----------------
struct TD { const float* src; float* dst; int R, C, ldD, tilesX, tileOff; };
struct TDPack { TD d[10]; };

__global__ void k_tmulti(TDPack P, int ndesc)
{
    __shared__ float smt[32][33];
    int bid = blockIdx.x;
    int di = 0;
    for (int i = 1; i < ndesc; i++) if (bid >= P.d[i].tileOff) di = i;
    const TD& D = P.d[di];
    int ti = bid - D.tileOff;
    int c0 = (ti % D.tilesX) * 32;
    int r0 = (ti / D.tilesX) * 32;
    int tx = threadIdx.x & 31, ty = threadIdx.x >> 5;
#pragma unroll
    for (int i = 0; i < 4; i++) {
        int r = r0 + ty + i * 8, c = c0 + tx;
        smt[ty + i * 8][tx] = (r < D.R && c < D.C) ? rtf(D.src[(size_t)r * D.C + c]) : 0.0f;
    }
    __syncthreads();
#pragma unroll
    for (int i = 0; i < 4; i++) {
        int c = c0 + ty + i * 8, r = r0 + tx;
        if (c < D.C && r < D.ldD) D.dst[(size_t)c * D.ldD + r] = smt[tx][ty + i * 8];
    }
}

// ---------------------------------------------------------------------------
// per-edge kernels
// ---------------------------------------------------------------------------
__global__ void k_nodemean(const float* __restrict__ x, float* __restrict__ nm)
{
    int n = blockIdx.x, tid = threadIdx.x;
    int lane = tid & 31, warp = tid >> 5;
    const float4* p = (const float4*)(x + (size_t)n * XLC);
    if (tid >= 49 && tid < 64) nm[n * KCG + tid] = 0.f;
    for (int l = warp; l < LF; l += 4) {
        float4 a = p[l * 32 + lane];
        float s = (a.x + a.y) + (a.z + a.w);
#pragma unroll
        for (int o = 16; o > 0; o >>= 1)
            s += __shfl_xor_sync(0xffffffffu, s, o);
        if (lane == 0) nm[n * KCG + l] = rtf(s * (1.0f / 128.0f));
    }
}

// gather node means to edges
__global__ void k_gather(const float* __restrict__ nm, const int* __restrict__ eidx,
                         float* __restrict__ xm, float* __restrict__ ym)
{
    int idx = blockIdx.x * 256 + threadIdx.x;
    if (idx >= NEDGE * KCG) return;
    int e = idx >> 6, tt = idx & 63;
    xm[idx] = nm[eidx[e] * KCG + tt];
    ym[idx] = nm[eidx[NEDGE + e] * KCG + tt];
}

// merged: mid[o] = sum_j ym[j]*t1[j*25+o]; A[o] = sum_j mid[j]*(t2+t3)[j*49+o]
__global__ void k_midcon(const float* __restrict__ ym, const float* __restrict__ t1,
                         const float* __restrict__ t2, const float* __restrict__ t3,
                         float* __restrict__ Aout)
{
    int e = blockIdx.x, tid = threadIdx.x;   // 64 threads
    __shared__ float ys[LF];
    __shared__ float ms[MMID];
    if (tid < LF) ys[tid] = ym[e * KCG + tid];
    __syncthreads();
    if (tid < MMID) {
        const float* tp = t1 + (size_t)e * TPAD + tid;
        float s = 0.0f;
#pragma unroll
        for (int j = 0; j < LF; j++) s = fmaf(ys[j], tp[j * MMID], s);
        ms[tid] = s;
    }
    __syncthreads();
    if (tid < LF) {
        const float* tp2 = t2 + (size_t)e * TPAD + tid;
        const float* tp3 = t3 + (size_t)e * TPAD + tid;
        float s = 0.0f;
#pragma unroll
        for (int j = 0; j < MMID; j++)
            s = fmaf(ms[j], tp2[j * LF] + tp3[j * LF], s);
        Aout[e * LF + tid] = s;
    }
}

// batched: blocks 0..4095 -> (node=src, other=dst); 4096..8191 -> swapped
__global__ void k_feat(const float* __restrict__ x, const float* __restrict__ glovec,
                       const float* __restrict__ wign, const int* __restrict__ eidx,
                       float* __restrict__ feat)
{
    int e2 = blockIdx.x, tid = threadIdx.x;
    int half = e2 >> 12;
    int e = e2 & 4095;
    __shared__ float wigS[256];
    __shared__ float gS[16];
    __shared__ float red[64];
    int node  = eidx[half ? (NEDGE + e) : e];
    int other = eidx[half ? e : (NEDGE + e)];
    wigS[tid]       = wign[e * 256 + tid];
    wigS[tid + 128] = wign[e * 256 + 128 + tid];
    if (tid < 16) gS[tid] = glovec[other * LR + tid];
    __syncthreads();

    float xr[16];
    const float* xp = x + (size_t)node * XLC;
#pragma unroll
    for (int j = 0; j < 16; j++) xr[j] = xp[j * 128 + tid];

    int lane = tid & 31, warp = tid >> 5;
    float* fp = feat + (size_t)e2 * FEATW;
#pragma unroll
    for (int i = 0; i < 16; i++) {
        float a = 0.0f;
#pragma unroll
        for (int j = 0; j < 16; j++) a = fmaf(wigS[j * 16 + i], xr[j], a);
        fp[i * 129 + tid] = rtf(a);
        float s = a;
#pragma unroll
        for (int o = 16; o > 0; o >>= 1) s += __shfl_xor_sync(0xffffffffu, s, o);
        if (lane == 0) red[i * 4 + warp] = s;
    }
    __syncthreads();
    if (tid < 16) {
        float s = red[tid * 4] + red[tid * 4 + 1] + red[tid * 4 + 2] + red[tid * 4 + 3];
        fp[tid * 129 + 128] = rtf(s * (1.0f / 128.0f) * gS[tid]);
    }
}

// fused: sh compute (wig_node @ (h2a+h2b)) + z-build + wigner rotate
__global__ __launch_bounds__(256)
void k_rotmsg(const float* __restrict__ x, const int* __restrict__ eidx,
              const float* __restrict__ Aarr, const float* __restrict__ h2,
              const float* __restrict__ wign, const float* __restrict__ wigner,
              float* __restrict__ msg)
{
    int e = blockIdx.x, tid = threadIdx.x;
    __shared__ float zs[LF * 128];
    __shared__ float wgS[48 * 49];
    __shared__ float As_[LF];
    __shared__ float wigS[256];
    int src = eidx[e], dst = eidx[NEDGE + e];
    const float4* xs4 = (const float4*)(x + (size_t)src * XLC);
    const float4* xt4 = (const float4*)(x + (size_t)dst * XLC);
    wigS[tid] = wign[e * 256 + tid];
    if (tid < LF) As_[tid] = Aarr[e * LF + tid];
    __syncthreads();

    float4* zs4 = (float4*)zs;
    for (int i4 = tid; i4 < LF * 32; i4 += 256) {
        int l = i4 >> 5;
        float4 a = xs4[i4], b = xt4[i4];
        float al = As_[l];
        float4 v;
        v.x = 2.0f * (a.x + b.x) + al;
        v.y = 2.0f * (a.y + b.y) + al;
        v.z = 2.0f * (a.z + b.z) + al;
        v.w = 2.0f * (a.w + b.w) + al;
        zs4[i4] = v;
    }
    const float4* wp4 = (const float4*)(wigner + (size_t)e * (48 * 49));
    float4* wg4 = (float4*)wgS;
    for (int i4 = tid; i4 < 588; i4 += 256) wg4[i4] = wp4[i4];
    __syncthreads();

    if (tid < 128) {
        float hr[16];
        const float* hpa = h2 + (size_t)e * MSGW;
        const float* hpb = h2 + (size_t)(e + NEDGE) * MSGW;
#pragma unroll
        for (int j = 0; j < 16; j++) hr[j] = hpa[j * 128 + tid] + hpb[j * 128 + tid];
#pragma unroll
        for (int i = 0; i < 16; i++) {
            float s = 0.0f;
#pragma unroll
            for (int j = 0; j < 16; j++) s = fmaf(wigS[i * 16 + j], hr[j], s);
            zs[i * 128 + tid] += s;
        }
    }
    __syncthreads();

    int cg = tid & 63, grp = tid >> 6;
    float2 acc[12];
#pragma unroll
    for (int rr = 0; rr < 12; rr++) { acc[rr].x = 0.0f; acc[rr].y = 0.0f; }
    const float2* z2 = (const float2*)zs;
    for (int l = 0; l < LF; l++) {
        float2 zv = z2[l * 64 + cg];
#pragma unroll
        for (int rr = 0; rr < 12; rr++) {
            float w = wgS[(grp * 12 + rr) * LF + l];
            acc[rr].x = fmaf(w, zv.x, acc[rr].x);
            acc[rr].y = fmaf(w, zv.y, acc[rr].y);
        }
    }
    float* mp = msg + (size_t)e * (NYR * MSGW);
#pragma unroll
    for (int rr = 0; rr < 12; rr++) {
        int row = grp * 12 + rr;
        float2 o; o.x = rtf(acc[rr].x); o.y = rtf(acc[rr].y);
        ((float2*)(mp + row * 128))[cg] = o;
    }
}

__global__ __launch_bounds__(256)
void k_out(const float* __restrict__ m2, const float* __restrict__ winv,
           float* __restrict__ out)
{
    int e = blockIdx.x, tid = threadIdx.x;
    __shared__ float mmS[16 * 128];
    __shared__ float wvS[LF * 16];
    const float4* mp4 = (const float4*)(m2 + (size_t)e * (NYR * MSGW));
    float4* mm4 = (float4*)mmS;
    for (int i4 = tid; i4 < 512; i4 += 256) {
        float4 a = mp4[i4], b = mp4[i4 + 512], c = mp4[i4 + 1024];
        float4 v;
        v.x = (a.x + b.x + c.x) * (1.0f / 3.0f);
        v.y = (a.y + b.y + c.y) * (1.0f / 3.0f);
        v.z = (a.z + b.z + c.z) * (1.0f / 3.0f);
        v.w = (a.w + b.w + c.w) * (1.0f / 3.0f);
        mm4[i4] = v;
    }
    const float4* wp4 = (const float4*)(winv + (size_t)e * (LF * 16));
    float4* wv4 = (float4*)wvS;
    for (int i4 = tid; i4 < 196; i4 += 256) wv4[i4] = wp4[i4];
    __syncthreads();

    const float INV3 = 0.5773502691896258f;
    int cg = tid & 63, grp = tid >> 6;
    const float2* mm2 = (const float2*)mmS;
    float* op = out + (size_t)e * XLC;
    for (int b = grp; b < LF; b += 4) {
        float2 s; s.x = 0.0f; s.y = 0.0f;
#pragma unroll
        for (int r = 0; r < 16; r++) {
            float w = wvS[b * 16 + r];
            float2 mv = mm2[r * 64 + cg];
            s.x = fmaf(w, mv.x, s.x);
            s.y = fmaf(w, mv.y, s.y);
        }
        s.x *= INV3; s.y *= INV3;
        ((float2*)(op + b * 128))[cg] = s;
    }
}

// ---------------------------------------------------------------------------
extern "C" void kernel_launch(void* const* d_in, const int* in_sizes, int n_in,
                              void* d_out, int out_size)
{
    const float* x      = (const float*)d_in[0];
    const float* glovec = (const float*)d_in[2];
    const float* x_edge = (const float*)d_in[3];
    const int*   eidx   = (const int*)  d_in[4];
    const float* W_cg1  = (const float*)d_in[8];
    const float* W_cg21 = (const float*)d_in[9];
    const float* W_cg22 = (const float*)d_in[10];
    const float* Wn1a   = (const float*)d_in[11];
    const float* bn1a   = (const float*)d_in[12];
    const float* Wn1b   = (const float*)d_in[13];
    const float* bn1b   = (const float*)d_in[14];
    const float* Wn2a   = (const float*)d_in[15];
    const float* bn2a   = (const float*)d_in[16];
    const float* Wn2b   = (const float*)d_in[17];
    const float* bn2b   = (const float*)d_in[18];
    const float* Wd     = (const float*)d_in[19];
    const float* bd     = (const float*)d_in[20];
    const float* Wp1    = (const float*)d_in[21];
    const float* bp1    = (const float*)d_in[22];
    const float* Wp2    = (const float*)d_in[23];
    const float* bp2    = (const float*)d_in[24];
    const float* wigner = (const float*)d_in[25];
    const float* winv   = (const float*)d_in[26];
    const float* wign   = (const float*)d_in[27];
    float* out = (float*)d_out;

    float *pWdT, *pW1aT, *pW1bT, *pW2aT, *pW2bT, *pWp1T, *pWp2T, *pWc1T, *pWc2T, *pWc3T;
    float *p_xer, *p_xe, *p_nm, *p_xm, *p_ym, *p_t3, *p_A, *p_feat, *p_h, *p_h2,
          *p_msg, *p_m1, *p_m2, *p_part;
    cudaGetSymbolAddress((void**)&pWdT,  g_WdT);
    cudaGetSymbolAddress((void**)&pW1aT, g_Wn1aT);
    cudaGetSymbolAddress((void**)&pW1bT, g_Wn1bT);
    cudaGetSymbolAddress((void**)&pW2aT, g_Wn2aT);
    cudaGetSymbolAddress((void**)&pW2bT, g_Wn2bT);
    cudaGetSymbolAddress((void**)&pWp1T, g_Wp1T);
    cudaGetSymbolAddress((void**)&pWp2T, g_Wp2T);
    cudaGetSymbolAddress((void**)&pWc1T, g_Wc1T);
    cudaGetSymbolAddress((void**)&pWc2T, g_Wc2T);
    cudaGetSymbolAddress((void**)&pWc3T, g_Wc3T);
    cudaGetSymbolAddress((void**)&p_xer,  g_xer);
    cudaGetSymbolAddress((void**)&p_xe,   g_xe);
    cudaGetSymbolAddress((void**)&p_nm,   g_nm);
    cudaGetSymbolAddress((void**)&p_xm,   g_xm);
    cudaGetSymbolAddress((void**)&p_ym,   g_ym);
    cudaGetSymbolAddress((void**)&p_t3,   g_t3);
    cudaGetSymbolAddress((void**)&p_A,    g_A);
    cudaGetSymbolAddress((void**)&p_feat, g_feat);
    cudaGetSymbolAddress((void**)&p_h,    g_h);
    cudaGetSymbolAddress((void**)&p_h2,   g_h2);
    cudaGetSymbolAddress((void**)&p_msg,  g_msg);
    cudaGetSymbolAddress((void**)&p_m1,   g_m1);
    cudaGetSymbolAddress((void**)&p_m2,   g_m2);
    cudaGetSymbolAddress((void**)&p_part, g_part);

    cudaFuncSetAttribute(tgemm<0>, cudaFuncAttributeMaxDynamicSharedMemorySize, DYN_SMEM);
    cudaFuncSetAttribute(tgemm<1>, cudaFuncAttributeMaxDynamicSharedMemorySize, DYN_SMEM);
    cudaFuncSetAttribute(tgemm<2>, cudaFuncAttributeMaxDynamicSharedMemorySize, DYN_SMEM);

    const int BIG = 1 << 30;

    // ---- weight transposes (tf32-rounded) + x_edge rounding ----
    {
        TDPack P;
        auto set = [&](int i, const float* s, float* dst, int R, int C, int ldD, int& off) {
            int tx = (C + 31) / 32, ty = (ldD + 31) / 32;
            P.d[i] = TD{ s, dst, R, C, ldD, tx, off };
            off += tx * ty;
        };
        int off = 0;
        set(0, Wd,    pWdT,  128,  128,  128,  off);
        set(1, Wn1a,  pW1aT, FEATW,128,  FEATW,off);
        set(2, Wn1b,  pW1bT, 128,  2048, 128,  off);
        set(3, Wn2a,  pW2aT, FEATW,128,  FEATW,off);
        set(4, Wn2b,  pW2bT, 128,  2048, 128,  off);
        set(5, Wp1,   pWp1T, 2048, 128,  2048, off);
        set(6, Wp2,   pWp2T, 128,  2048, 128,  off);
        set(7, W_cg1, pWc1T, 49,   1225, KCG,  off);
        set(8, W_cg21,pWc2T, 49,   1225, KCG,  off);
        set(9, W_cg22,pWc3T, 49,   1225, KCG,  off);
        k_tmulti<<<off, 256>>>(P, 10);
    }
    k_round<<<(NEDGE * 128 + 255) / 256, 256>>>(x_edge, p_xer, NEDGE * 128);

    // 1. xe = silu(x_edge @ Wd + bd)
    tgemm<1><<<dim3(1, 32, 1), 128, DYN_SMEM>>>(
        p_xer, nullptr, nullptr, pWdT, nullptr, nullptr, bd, nullptr, nullptr,
        p_xe, NEDGE, 128, 128, 128, 4, 4, 0, BIG);

    // 2. per-node channel means, gathered to edges
    k_nodemean<<<NNODE, 128>>>(x, p_nm);
    k_gather<<<(NEDGE * KCG + 255) / 256, 256>>>(p_nm, eidx, p_xm, p_ym);

    // 3. CG bilinears: batched z=3, then fused mid+contract
    tgemm<0><<<dim3(10, 32, 3), 128, DYN_SMEM>>>(
        p_xm, p_xm, p_ym, pWc1T, pWc2T, pWc3T, nullptr, nullptr, nullptr,
        p_t3, NEDGE, 1225, KCG, TPAD, 2, 2, 1, BIG);
    k_midcon<<<NEDGE, 64>>>(p_ym, p_t3, p_t3 + (size_t)NEDGE * TPAD,
                            p_t3 + 2 * (size_t)NEDGE * TPAD, p_A);

    // 4+5. node_interactions batched
    k_feat<<<2 * NEDGE, 128>>>(x, glovec, wign, eidx, p_feat);
    tgemm<0><<<dim3(1, 64, 4), 128, DYN_SMEM>>>(
        p_feat, nullptr, nullptr, pW1aT, pW2aT, nullptr, nullptr, nullptr, nullptr,
        p_part, 2 * NEDGE, 128, FEATW, 128, 65, 17, 0, 32);
    k_combine<1><<<(2 * NEDGE * 128 + 255) / 256, 256>>>(
        p_part, bn1a, bn2a, nullptr, p_h, 2 * NEDGE, 4, NEDGE);
    tgemm<1><<<dim3(16, 64, 1), 128, DYN_SMEM>>>(
        p_h, nullptr, nullptr, pW1bT, pW2bT, nullptr, bn1b, bn2b, nullptr,
        p_h2, 2 * NEDGE, 2048, 128, 2048, 4, 4, 0, 32);

    // 6. fused sh + z-build + rotate (msg tf32-rounded for Wp1 GEMM)
    k_rotmsg<<<NEDGE, 256>>>(x, eidx, p_A, p_h2, wign, wigner, p_msg);

    // 7. edge MLP
    tgemm<0><<<dim3(1, 96, 2), 128, DYN_SMEM>>>(
        p_msg, nullptr, nullptr, pWp1T, nullptr, nullptr, nullptr, nullptr, nullptr,
        p_part, NEDGE * NYR, 128, 2048, 128, 64, 32, 0, BIG);
    k_combine<2><<<(NEDGE * NYR * 128 + 255) / 256, 256>>>(
        p_part, bp1, bp1, p_xe, p_m1, NEDGE * NYR, 2, BIG);
    tgemm<1><<<dim3(16, 96, 1), 128, DYN_SMEM>>>(
        p_m1, nullptr, nullptr, pWp2T, nullptr, nullptr, bp2, nullptr, nullptr,
        p_m2, NEDGE * NYR, 2048, 128, 2048, 4, 4, 0, BIG);

    // 8. NY-mean + inverse rotation
    k_out<<<NEDGE, 256>>>(p_m2, winv, out);
}

// round 17
// speedup vs baseline: 1.5351x; 1.0104x over previous
#include <cuda_runtime.h>
#include <cstdint>
#include <math.h>

// ---------------- problem constants ----------------
#define NNODE 2048
#define NEDGE 4096
#define LF    49
#define LR    16
#define MMID  25
#define NYR   3
#define CCH   128
#define HID   128
#define XLC   (LF*CCH)      // 6272
#define FEATW 2064          // 16*129
#define MSGW  2048          // 16*128
#define TPAD  1280          // padded 1225
#define KCG   64            // padded 49

// ---------------- device scratch ----------------
__device__ __align__(16) float g_WdT  [128*128];
__device__ __align__(16) float g_Wn1aT[128*FEATW];
__device__ __align__(16) float g_Wn1bT[2048*128];
__device__ __align__(16) float g_Wn2aT[128*FEATW];
__device__ __align__(16) float g_Wn2bT[2048*128];
__device__ __align__(16) float g_Wp1T [128*2048];
__device__ __align__(16) float g_Wp2T [2048*128];
__device__ __align__(16) float g_Wc1T [TPAD*KCG];
__device__ __align__(16) float g_Wc2T [TPAD*KCG];
__device__ __align__(16) float g_Wc3T [TPAD*KCG];
__device__ __align__(16) float g_xer  [NEDGE*128];
__device__ __align__(16) float g_xe   [NEDGE*HID];
__device__ __align__(16) float g_nm   [NNODE*KCG];
__device__ __align__(16) float g_xm   [NEDGE*KCG];
__device__ __align__(16) float g_ym   [NEDGE*KCG];
__device__ __align__(16) float g_t3   [3*NEDGE*TPAD];
__device__ __align__(16) float g_A    [NEDGE*LF];
__device__ __align__(16) float g_feat [2*NEDGE*FEATW];
__device__ __align__(16) float g_h    [2*NEDGE*HID];
__device__ __align__(16) float g_h2   [2*NEDGE*MSGW];
__device__ __align__(16) float g_msg  [NEDGE*NYR*MSGW];
__device__ __align__(16) float g_m1   [NEDGE*NYR*HID];
__device__ __align__(16) float g_m2   [NEDGE*NYR*MSGW];
__device__ __align__(16) float g_part [4*12288*128];

__device__ __forceinline__ float silu_f(float v) { return v / (1.0f + __expf(-v)); }

// round fp32 -> nearest tf32 value (kept in fp32 container)
__device__ __forceinline__ float rtf(float f) {
    uint32_t r;
    asm("cvt.rna.tf32.f32 %0, %1;" : "=r"(r) : "f"(f));
    return __uint_as_float(r);
}

__device__ __forceinline__ void mma8(float* d, uint32_t a0, uint32_t a1, uint32_t a2,
                                     uint32_t a3, uint32_t b0, uint32_t b1) {
    asm volatile(
        "mma.sync.aligned.m16n8k8.row.col.f32.tf32.tf32.f32 "
        "{%0,%1,%2,%3}, {%4,%5,%6,%7}, {%8,%9}, {%0,%1,%2,%3};"
        : "+f"(d[0]), "+f"(d[1]), "+f"(d[2]), "+f"(d[3])
        : "r"(a0), "r"(a1), "r"(a2), "r"(a3), "r"(b0), "r"(b1));
}

__device__ __forceinline__ void cp16(uint32_t dst, const float* src, bool pred) {
    int sz = pred ? 16 : 0;
    asm volatile("cp.async.cg.shared.global [%0], [%1], 16, %2;"
                 :: "r"(dst), "l"(src), "r"(sz) : "memory");
}
#define CP_COMMIT() asm volatile("cp.async.commit_group;" ::: "memory")
template<int N> __device__ __forceinline__ void cpwait() {
    asm volatile("cp.async.wait_group %0;" :: "n"(N) : "memory");
}

// ---------------------------------------------------------------------------
// tf32 mma.sync GEMM: 128 threads, 2x2 warps, warp tile 64x64, CTA 128x128,
// K-chunks 32, cp.async double buffer, kk-software-pipelined fragment loads.
// Inputs MUST be tf32-pre-rounded.
// zmode=0: grid.z = split-K (C + z*M*ldc); dual-B keyed on blockIdx.y/ysplit.
// zmode=1: grid.z = batch (A/B by z).
// EPI: 0=raw, 1=bias+silu, 2=bias+silu then *= xe[(row/3)*128+col]
// ---------------------------------------------------------------------------
#define LDA 36
#define ATILE (128*LDA)
#define BUFSZ (2*ATILE)
#define DYN_SMEM (2*BUFSZ*4)     // 73728 bytes per CTA; occ 2

template<int EPI>
__global__ __launch_bounds__(128, 2)
void tgemm(const float* __restrict__ A0, const float* __restrict__ A1,
           const float* __restrict__ A2,
           const float* __restrict__ B0, const float* __restrict__ B1,
           const float* __restrict__ B2,
           const float* __restrict__ bias0, const float* __restrict__ bias1,
           const float* __restrict__ xe,
           float* __restrict__ C, int M, int Nreal, int K, int ldc,
           int chunksTotal, int chunksPerZ, int zmode, int ysplit)
{
    extern __shared__ uint32_t sm[];
    const uint32_t smBase = (uint32_t)__cvta_generic_to_shared(sm);
    const int tid  = threadIdx.x;
    const int lane = tid & 31;
    const int warp = tid >> 5;           // 0..3
    const int wm = warp >> 1, wn = warp & 1;
    const int g = lane >> 2, t = lane & 3;

    const int bm0 = blockIdx.y * 128;
    const int bn0 = blockIdx.x * 128;
    const int z   = blockIdx.z;

    const float* A;
    const float* BT;
    const float* bias;
    int c0, cend;
    if (zmode) {
        A    = (z == 0) ? A0 : (z == 1) ? A1 : A2;
        BT   = (z == 0) ? B0 : (z == 1) ? B1 : B2;
        bias = bias0;
        c0 = 0; cend = chunksTotal;
    } else {
        A    = A0;
        BT   = ((int)blockIdx.y < ysplit) ? B0 : B1;
        bias = ((int)blockIdx.y < ysplit) ? bias0 : bias1;
        c0 = z * chunksPerZ;
        cend = c0 + chunksPerZ; if (cend > chunksTotal) cend = chunksTotal;
    }

    float acc[4][8][4];                  // warp tile 64x64
#pragma unroll
    for (int i = 0; i < 4; i++)
#pragma unroll
        for (int j = 0; j < 8; j++)
#pragma unroll
            for (int q = 0; q < 4; q++) acc[i][j][q] = 0.0f;

    const int lseg = tid & 7;

    auto issue = [&](int c, int b) {
        const int kbase = c * 32;
        const int gk = kbase + lseg * 4;
        const bool kok = gk < K;
        uint32_t As = smBase + (uint32_t)(b * BUFSZ) * 4;
        uint32_t Bs = As + ATILE * 4;
#pragma unroll
        for (int i = 0; i < 8; i++) {
            int idx = tid + i * 128;
            int r = idx >> 3;
            cp16(As + (uint32_t)(r * LDA + lseg * 4) * 4,
                 A + (size_t)(bm0 + r) * K + gk, kok);
        }
#pragma unroll
        for (int i = 0; i < 8; i++) {
            int idx = tid + i * 128;
            int r = idx >> 3;
            int gn = bn0 + r;
            cp16(Bs + (uint32_t)(r * LDA + lseg * 4) * 4,
                 BT + (size_t)gn * K + gk, kok && (gn < Nreal));
        }
        CP_COMMIT();
    };

    issue(c0, 0);
    for (int c = c0; c < cend; ++c) {
        int b = (c - c0) & 1;
        if (c + 1 < cend) { issue(c + 1, b ^ 1); cpwait<1>(); }
        else              { cpwait<0>(); }
        __syncthreads();

        const uint32_t* As = sm + b * BUFSZ;
        const uint32_t* Bs = As + ATILE;

        uint32_t af[2][4][4], bf[2][8][2];
        auto loadfrag = [&](int kk, int buf) {
            const int k0 = kk * 8;
#pragma unroll
            for (int i = 0; i < 4; i++) {
                int mb = wm * 64 + i * 16;
                af[buf][i][0] = As[(mb + g)     * LDA + k0 + t];
                af[buf][i][1] = As[(mb + g + 8) * LDA + k0 + t];
                af[buf][i][2] = As[(mb + g)     * LDA + k0 + t + 4];
                af[buf][i][3] = As[(mb + g + 8) * LDA + k0 + t + 4];
            }
#pragma unroll
            for (int j = 0; j < 8; j++) {
                int nb = wn * 64 + j * 8;
                bf[buf][j][0] = Bs[(nb + g) * LDA + k0 + t];
                bf[buf][j][1] = Bs[(nb + g) * LDA + k0 + t + 4];
            }
        };

        loadfrag(0, 0);
#pragma unroll
        for (int kk = 0; kk < 4; kk++) {
            int cur = kk & 1;
            if (kk < 3) loadfrag(kk + 1, cur ^ 1);
#pragma unroll
            for (int i = 0; i < 4; i++)
#pragma unroll
                for (int j = 0; j < 8; j++)
                    mma8(acc[i][j], af[cur][i][0], af[cur][i][1],
                         af[cur][i][2], af[cur][i][3],
                         bf[cur][j][0], bf[cur][j][1]);
        }
        __syncthreads();   // all warps done reading buf b before refill (c+2)
    }

    float* Cz = C + (size_t)z * M * ldc;
#pragma unroll
    for (int i = 0; i < 4; i++) {
        int r0 = bm0 + wm * 64 + i * 16 + g;
#pragma unroll
        for (int j = 0; j < 8; j++) {
            int cc = bn0 + wn * 64 + j * 8 + 2 * t;
#pragma unroll
            for (int half = 0; half < 2; half++) {
                int row = r0 + half * 8;
                float v0 = acc[i][j][half * 2 + 0];
                float v1 = acc[i][j][half * 2 + 1];
                if (cc < Nreal) {
                    if (EPI >= 1) {
                        v0 = silu_f(v0 + bias[cc]);
                        v1 = (cc + 1 < Nreal) ? silu_f(v1 + bias[cc + 1]) : 0.0f;
                    }
                    if (EPI == 2) {
                        const float* xr = xe + (size_t)(row / 3) * 128;
                        v0 *= xr[cc];
                        if (cc + 1 < Nreal) v1 *= xr[cc + 1];
                    }
                    float* cp = Cz + (size_t)row * ldc + cc;
                    if (cc + 1 < Nreal) { float2 fv = make_float2(v0, v1); *(float2*)cp = fv; }
                    else cp[0] = v0;
                }
            }
        }
    }
}

// combine split-K partials (float4-vectorized): out = epi(sum_z part[z]+bias)
// grid covers M*32 float4 elements. bias1 used for rows >= Mhalf.
template<int EPI>
__global__ void k_combine(const float* __restrict__ part, const float* __restrict__ bias0,
                          const float* __restrict__ bias1, const float* __restrict__ xe,
                          float* __restrict__ outp, int M, int nsplit, int Mhalf)
{
    int i4 = blockIdx.x * 256 + threadIdx.x;
    if (i4 >= M * 32) return;
    int m = i4 >> 5, n4 = (i4 & 31) * 4;
    const float* bias = (m < Mhalf) ? bias0 : bias1;
    float4 s = *(const float4*)(bias + n4);
    for (int zz = 0; zz < nsplit; zz++) {
        float4 p = *(const float4*)(part + (size_t)zz * M * 128 + (size_t)i4 * 4);
        s.x += p.x; s.y += p.y; s.z += p.z; s.w += p.w;
    }
    s.x = silu_f(s.x); s.y = silu_f(s.y); s.z = silu_f(s.z); s.w = silu_f(s.w);
    if (EPI == 2) {
        const float4 xr = *(const float4*)(xe + (size_t)(m / 3) * 128 + n4);
        s.x *= xr.x; s.y *= xr.y; s.z *= xr.z; s.w *= xr.w;
    }
    float4 o;
    o.x = rtf(s.x); o.y = rtf(s.y); o.z = rtf(s.z); o.w = rtf(s.w);
    *(float4*)(outp + (size_t)i4 * 4) = o;
}

// tf32-round a buffer
__global__ void k_round(const float* __restrict__ src, float* __restrict__ dst, int n)
{
    int i = blockIdx.x * 256 + threadIdx.x;
    if (i < n) dst[i] = rtf(src[i]);
}

// ---------------- fused multi-transpose (tf32-rounded output) ----------------
struct TD { const float* src; float* dst; int R, C, ldD, tilesX, tileOff; };
struct TDPack { TD d[10]; };

__global__ void k_tmulti(TDPack P, int ndesc)
{
    __shared__ float smt[32][33];
    int bid = blockIdx.x;
    int di = 0;
    for (int i = 1; i < ndesc; i++) if (bid >= P.d[i].tileOff) di = i;
    const TD& D = P.d[di];
    int ti = bid - D.tileOff;
    int c0 = (ti % D.tilesX) * 32;
    int r0 = (ti / D.tilesX) * 32;
    int tx = threadIdx.x & 31, ty = threadIdx.x >> 5;
#pragma unroll
    for (int i = 0; i < 4; i++) {
        int r = r0 + ty + i * 8, c = c0 + tx;
        smt[ty + i * 8][tx] = (r < D.R && c < D.C) ? rtf(D.src[(size_t)r * D.C + c]) : 0.0f;
    }
    __syncthreads();
#pragma unroll
    for (int i = 0; i < 4; i++) {
        int c = c0 + ty + i * 8, r = r0 + tx;
        if (c < D.C && r < D.ldD) D.dst[(size_t)c * D.ldD + r] = smt[tx][ty + i * 8];
    }
}

// ---------------------------------------------------------------------------
// per-edge kernels
// ---------------------------------------------------------------------------
__global__ void k_nodemean(const float* __restrict__ x, float* __restrict__ nm)
{
    int n = blockIdx.x, tid = threadIdx.x;
    int lane = tid & 31, warp = tid >> 5;
    const float4* p = (const float4*)(x + (size_t)n * XLC);
    if (tid >= 49 && tid < 64) nm[n * KCG + tid] = 0.f;
    for (int l = warp; l < LF; l += 4) {
        float4 a = p[l * 32 + lane];
        float s = (a.x + a.y) + (a.z + a.w);
#pragma unroll
        for (int o = 16; o > 0; o >>= 1)
            s += __shfl_xor_sync(0xffffffffu, s, o);
        if (lane == 0) nm[n * KCG + l] = rtf(s * (1.0f / 128.0f));
    }
}

// gather node means to edges (float4: 16 float4 per edge row)
__global__ void k_gather(const float* __restrict__ nm, const int* __restrict__ eidx,
                         float* __restrict__ xm, float* __restrict__ ym)
{
    int i4 = blockIdx.x * 256 + threadIdx.x;
    if (i4 >= NEDGE * 16) return;
    int e = i4 >> 4, tt = i4 & 15;
    const float4* nm4 = (const float4*)nm;
    ((float4*)xm)[i4] = nm4[eidx[e] * 16 + tt];
    ((float4*)ym)[i4] = nm4[eidx[NEDGE + e] * 16 + tt];
}

// merged: mid[o] = sum_j ym[j]*t1[j*25+o]; A[o] = sum_j mid[j]*(t2+t3)[j*49+o]
__global__ void k_midcon(const float* __restrict__ ym, const float* __restrict__ t1,
                         const float* __restrict__ t2, const float* __restrict__ t3,
                         float* __restrict__ Aout)
{
    int e = blockIdx.x, tid = threadIdx.x;   // 64 threads
    __shared__ float ys[LF];
    __shared__ float ms[MMID];
    if (tid < LF) ys[tid] = ym[e * KCG + tid];
    __syncthreads();
    if (tid < MMID) {
        const float* tp = t1 + (size_t)e * TPAD + tid;
        float s = 0.0f;
#pragma unroll
        for (int j = 0; j < LF; j++) s = fmaf(ys[j], tp[j * MMID], s);
        ms[tid] = s;
    }
    __syncthreads();
    if (tid < LF) {
        const float* tp2 = t2 + (size_t)e * TPAD + tid;
        const float* tp3 = t3 + (size_t)e * TPAD + tid;
        float s = 0.0f;
#pragma unroll
        for (int j = 0; j < MMID; j++)
            s = fmaf(ms[j], tp2[j * LF] + tp3[j * LF], s);
        Aout[e * LF + tid] = s;
    }
}

// batched: blocks 0..4095 -> (node=src, other=dst); 4096..8191 -> swapped
__global__ void k_feat(const float* __restrict__ x, const float* __restrict__ glovec,
                       const float* __restrict__ wign, const int* __restrict__ eidx,
                       float* __restrict__ feat)
{
    int e2 = blockIdx.x, tid = threadIdx.x;
    int half = e2 >> 12;
    int e = e2 & 4095;
    __shared__ float wigS[256];
    __shared__ float gS[16];
    __shared__ float red[64];
    int node  = eidx[half ? (NEDGE + e) : e];
    int other = eidx[half ? e : (NEDGE + e)];
    wigS[tid]       = wign[e * 256 + tid];
    wigS[tid + 128] = wign[e * 256 + 128 + tid];
    if (tid < 16) gS[tid] = glovec[other * LR + tid];
    __syncthreads();

    float xr[16];
    const float* xp = x + (size_t)node * XLC;
#pragma unroll
    for (int j = 0; j < 16; j++) xr[j] = xp[j * 128 + tid];

    int lane = tid & 31, warp = tid >> 5;
    float* fp = feat + (size_t)e2 * FEATW;
#pragma unroll
    for (int i = 0; i < 16; i++) {
        float a = 0.0f;
#pragma unroll
        for (int j = 0; j < 16; j++) a = fmaf(wigS[j * 16 + i], xr[j], a);
        fp[i * 129 + tid] = rtf(a);
        float s = a;
#pragma unroll
        for (int o = 16; o > 0; o >>= 1) s += __shfl_xor_sync(0xffffffffu, s, o);
        if (lane == 0) red[i * 4 + warp] = s;
    }
    __syncthreads();
    if (tid < 16) {
        float s = red[tid * 4] + red[tid * 4 + 1] + red[tid * 4 + 2] + red[tid * 4 + 3];
        fp[tid * 129 + 128] = rtf(s * (1.0f / 128.0f) * gS[tid]);
    }
}

// fused: sh compute (wig_node @ (h2a+h2b)) + z-build + wigner rotate
__global__ __launch_bounds__(256)
void k_rotmsg(const float* __restrict__ x, const int* __restrict__ eidx,
              const float* __restrict__ Aarr, const float* __restrict__ h2,
              const float* __restrict__ wign, const float* __restrict__ wigner,
              float* __restrict__ msg)
{
    int e = blockIdx.x, tid = threadIdx.x;
    __shared__ float zs[LF * 128];
    __shared__ float wgS[48 * 49];
    __shared__ float As_[LF];
    __shared__ float wigS[256];
    int src = eidx[e], dst = eidx[NEDGE + e];
    const float4* xs4 = (const float4*)(x + (size_t)src * XLC);
    const float4* xt4 = (const float4*)(x + (size_t)dst * XLC);
    wigS[tid] = wign[e * 256 + tid];
    if (tid < LF) As_[tid] = Aarr[e * LF + tid];
    __syncthreads();

    float4* zs4 = (float4*)zs;
    for (int i4 = tid; i4 < LF * 32; i4 += 256) {
        int l = i4 >> 5;
        float4 a = xs4[i4], b = xt4[i4];
        float al = As_[l];
        float4 v;
        v.x = 2.0f * (a.x + b.x) + al;
        v.y = 2.0f * (a.y + b.y) + al;
        v.z = 2.0f * (a.z + b.z) + al;
        v.w = 2.0f * (a.w + b.w) + al;
        zs4[i4] = v;
    }
    const float4* wp4 = (const float4*)(wigner + (size_t)e * (48 * 49));
    float4* wg4 = (float4*)wgS;
    for (int i4 = tid; i4 < 588; i4 += 256) wg4[i4] = wp4[i4];
    __syncthreads();

    if (tid < 128) {
        float hr[16];
        const float* hpa = h2 + (size_t)e * MSGW;
        const float* hpb = h2 + (size_t)(e + NEDGE) * MSGW;
#pragma unroll
        for (int j = 0; j < 16; j++) hr[j] = hpa[j * 128 + tid] + hpb[j * 128 + tid];
#pragma unroll
        for (int i = 0; i < 16; i++) {
            float s = 0.0f;
#pragma unroll
            for (int j = 0; j < 16; j++) s = fmaf(wigS[i * 16 + j], hr[j], s);
            zs[i * 128 + tid] += s;
        }
    }
    __syncthreads();

    int cg = tid & 63, grp = tid >> 6;
    float2 acc[12];
#pragma unroll
    for (int rr = 0; rr < 12; rr++) { acc[rr].x = 0.0f; acc[rr].y = 0.0f; }
    const float2* z2 = (const float2*)zs;
    for (int l = 0; l < LF; l++) {
        float2 zv = z2[l * 64 + cg];
#pragma unroll
        for (int rr = 0; rr < 12; rr++) {
            float w = wgS[(grp * 12 + rr) * LF + l];
            acc[rr].x = fmaf(w, zv.x, acc[rr].x);
            acc[rr].y = fmaf(w, zv.y, acc[rr].y);
        }
    }
    float* mp = msg + (size_t)e * (NYR * MSGW);
#pragma unroll
    for (int rr = 0; rr < 12; rr++) {
        int row = grp * 12 + rr;
        float2 o; o.x = rtf(acc[rr].x); o.y = rtf(acc[rr].y);
        ((float2*)(mp + row * 128))[cg] = o;
    }
}

__global__ __launch_bounds__(256)
void k_out(const float* __restrict__ m2, const float* __restrict__ winv,
           float* __restrict__ out)
{
    int e = blockIdx.x, tid = threadIdx.x;
    __shared__ float mmS[16 * 128];
    __shared__ float wvS[LF * 16];
    const float4* mp4 = (const float4*)(m2 + (size_t)e * (NYR * MSGW));
    float4* mm4 = (float4*)mmS;
    for (int i4 = tid; i4 < 512; i4 += 256) {
        float4 a = mp4[i4], b = mp4[i4 + 512], c = mp4[i4 + 1024];
        float4 v;
        v.x = (a.x + b.x + c.x) * (1.0f / 3.0f);
        v.y = (a.y + b.y + c.y) * (1.0f / 3.0f);
        v.z = (a.z + b.z + c.z) * (1.0f / 3.0f);
        v.w = (a.w + b.w + c.w) * (1.0f / 3.0f);
        mm4[i4] = v;
    }
    const float4* wp4 = (const float4*)(winv + (size_t)e * (LF * 16));
    float4* wv4 = (float4*)wvS;
    for (int i4 = tid; i4 < 196; i4 += 256) wv4[i4] = wp4[i4];
    __syncthreads();

    const float INV3 = 0.5773502691896258f;
    int cg = tid & 63, grp = tid >> 6;
    const float2* mm2 = (const float2*)mmS;
    float* op = out + (size_t)e * XLC;
    for (int b = grp; b < LF; b += 4) {
        float2 s; s.x = 0.0f; s.y = 0.0f;
#pragma unroll
        for (int r = 0; r < 16; r++) {
            float w = wvS[b * 16 + r];
            float2 mv = mm2[r * 64 + cg];
            s.x = fmaf(w, mv.x, s.x);
            s.y = fmaf(w, mv.y, s.y);
        }
        s.x *= INV3; s.y *= INV3;
        ((float2*)(op + b * 128))[cg] = s;
    }
}

// ---------------------------------------------------------------------------
extern "C" void kernel_launch(void* const* d_in, const int* in_sizes, int n_in,
                              void* d_out, int out_size)
{
    const float* x      = (const float*)d_in[0];
    const float* glovec = (const float*)d_in[2];
    const float* x_edge = (const float*)d_in[3];
    const int*   eidx   = (const int*)  d_in[4];
    const float* W_cg1  = (const float*)d_in[8];
    const float* W_cg21 = (const float*)d_in[9];
    const float* W_cg22 = (const float*)d_in[10];
    const float* Wn1a   = (const float*)d_in[11];
    const float* bn1a   = (const float*)d_in[12];
    const float* Wn1b   = (const float*)d_in[13];
    const float* bn1b   = (const float*)d_in[14];
    const float* Wn2a   = (const float*)d_in[15];
    const float* bn2a   = (const float*)d_in[16];
    const float* Wn2b   = (const float*)d_in[17];
    const float* bn2b   = (const float*)d_in[18];
    const float* Wd     = (const float*)d_in[19];
    const float* bd     = (const float*)d_in[20];
    const float* Wp1    = (const float*)d_in[21];
    const float* bp1    = (const float*)d_in[22];
    const float* Wp2    = (const float*)d_in[23];
    const float* bp2    = (const float*)d_in[24];
    const float* wigner = (const float*)d_in[25];
    const float* winv   = (const float*)d_in[26];
    const float* wign   = (const float*)d_in[27];
    float* out = (float*)d_out;

    float *pWdT, *pW1aT, *pW1bT, *pW2aT, *pW2bT, *pWp1T, *pWp2T, *pWc1T, *pWc2T, *pWc3T;
    float *p_xer, *p_xe, *p_nm, *p_xm, *p_ym, *p_t3, *p_A, *p_feat, *p_h, *p_h2,
          *p_msg, *p_m1, *p_m2, *p_part;
    cudaGetSymbolAddress((void**)&pWdT,  g_WdT);
    cudaGetSymbolAddress((void**)&pW1aT, g_Wn1aT);
    cudaGetSymbolAddress((void**)&pW1bT, g_Wn1bT);
    cudaGetSymbolAddress((void**)&pW2aT, g_Wn2aT);
    cudaGetSymbolAddress((void**)&pW2bT, g_Wn2bT);
    cudaGetSymbolAddress((void**)&pWp1T, g_Wp1T);
    cudaGetSymbolAddress((void**)&pWp2T, g_Wp2T);
    cudaGetSymbolAddress((void**)&pWc1T, g_Wc1T);
    cudaGetSymbolAddress((void**)&pWc2T, g_Wc2T);
    cudaGetSymbolAddress((void**)&pWc3T, g_Wc3T);
    cudaGetSymbolAddress((void**)&p_xer,  g_xer);
    cudaGetSymbolAddress((void**)&p_xe,   g_xe);
    cudaGetSymbolAddress((void**)&p_nm,   g_nm);
    cudaGetSymbolAddress((void**)&p_xm,   g_xm);
    cudaGetSymbolAddress((void**)&p_ym,   g_ym);
    cudaGetSymbolAddress((void**)&p_t3,   g_t3);
    cudaGetSymbolAddress((void**)&p_A,    g_A);
    cudaGetSymbolAddress((void**)&p_feat, g_feat);
    cudaGetSymbolAddress((void**)&p_h,    g_h);
    cudaGetSymbolAddress((void**)&p_h2,   g_h2);
    cudaGetSymbolAddress((void**)&p_msg,  g_msg);
    cudaGetSymbolAddress((void**)&p_m1,   g_m1);
    cudaGetSymbolAddress((void**)&p_m2,   g_m2);
    cudaGetSymbolAddress((void**)&p_part, g_part);

    cudaFuncSetAttribute(tgemm<0>, cudaFuncAttributeMaxDynamicSharedMemorySize, DYN_SMEM);
    cudaFuncSetAttribute(tgemm<1>, cudaFuncAttributeMaxDynamicSharedMemorySize, DYN_SMEM);
    cudaFuncSetAttribute(tgemm<2>, cudaFuncAttributeMaxDynamicSharedMemorySize, DYN_SMEM);

    const int BIG = 1 << 30;

    // ---- weight transposes (tf32-rounded) + x_edge rounding ----
    {
        TDPack P;
        auto set = [&](int i, const float* s, float* dst, int R, int C, int ldD, int& off) {
            int tx = (C + 31) / 32, ty = (ldD + 31) / 32;
            P.d[i] = TD{ s, dst, R, C, ldD, tx, off };
            off += tx * ty;
        };
        int off = 0;
        set(0, Wd,    pWdT,  128,  128,  128,  off);
        set(1, Wn1a,  pW1aT, FEATW,128,  FEATW,off);
        set(2, Wn1b,  pW1bT, 128,  2048, 128,  off);
        set(3, Wn2a,  pW2aT, FEATW,128,  FEATW,off);
        set(4, Wn2b,  pW2bT, 128,  2048, 128,  off);
        set(5, Wp1,   pWp1T, 2048, 128,  2048, off);
        set(6, Wp2,   pWp2T, 128,  2048, 128,  off);
        set(7, W_cg1, pWc1T, 49,   1225, KCG,  off);
        set(8, W_cg21,pWc2T, 49,   1225, KCG,  off);
        set(9, W_cg22,pWc3T, 49,   1225, KCG,  off);
        k_tmulti<<<off, 256>>>(P, 10);
    }
    k_round<<<(NEDGE * 128 + 255) / 256, 256>>>(x_edge, p_xer, NEDGE * 128);

    // 1. xe = silu(x_edge @ Wd + bd)
    tgemm<1><<<dim3(1, 32, 1), 128, DYN_SMEM>>>(
        p_xer, nullptr, nullptr, pWdT, nullptr, nullptr, bd, nullptr, nullptr,
        p_xe, NEDGE, 128, 128, 128, 4, 4, 0, BIG);

    // 2. per-node channel means, gathered to edges
    k_nodemean<<<NNODE, 128>>>(x, p_nm);
    k_gather<<<(NEDGE * 16 + 255) / 256, 256>>>(p_nm, eidx, p_xm, p_ym);

    // 3. CG bilinears: batched z=3, then fused mid+contract
    tgemm<0><<<dim3(10, 32, 3), 128, DYN_SMEM>>>(
        p_xm, p_xm, p_ym, pWc1T, pWc2T, pWc3T, nullptr, nullptr, nullptr,
        p_t3, NEDGE, 1225, KCG, TPAD, 2, 2, 1, BIG);
    k_midcon<<<NEDGE, 64>>>(p_ym, p_t3, p_t3 + (size_t)NEDGE * TPAD,
                            p_t3 + 2 * (size_t)NEDGE * TPAD, p_A);

    // 4+5. node_interactions batched
    k_feat<<<2 * NEDGE, 128>>>(x, glovec, wign, eidx, p_feat);
    tgemm<0><<<dim3(1, 64, 4), 128, DYN_SMEM>>>(
        p_feat, nullptr, nullptr, pW1aT, pW2aT, nullptr, nullptr, nullptr, nullptr,
        p_part, 2 * NEDGE, 128, FEATW, 128, 65, 17, 0, 32);
    k_combine<1><<<(2 * NEDGE * 32 + 255) / 256, 256>>>(
        p_part, bn1a, bn2a, nullptr, p_h, 2 * NEDGE, 4, NEDGE);
    tgemm<1><<<dim3(16, 64, 1), 128, DYN_SMEM>>>(
        p_h, nullptr, nullptr, pW1bT, pW2bT, nullptr, bn1b, bn2b, nullptr,
        p_h2, 2 * NEDGE, 2048, 128, 2048, 4, 4, 0, 32);

    // 6. fused sh + z-build + rotate (msg tf32-rounded for Wp1 GEMM)
    k_rotmsg<<<NEDGE, 256>>>(x, eidx, p_A, p_h2, wign, wigner, p_msg);

    // 7. edge MLP
    tgemm<0><<<dim3(1, 96, 2), 128, DYN_SMEM>>>(
        p_msg, nullptr, nullptr, pWp1T, nullptr, nullptr, nullptr, nullptr, nullptr,
        p_part, NEDGE * NYR, 128, 2048, 128, 64, 32, 0, BIG);
    k_combine<2><<<(NEDGE * NYR * 32 + 255) / 256, 256>>>(
        p_part, bp1, bp1, p_xe, p_m1, NEDGE * NYR, 2, BIG);
    tgemm<1><<<dim3(16, 96, 1), 128, DYN_SMEM>>>(
        p_m1, nullptr, nullptr, pWp2T, nullptr, nullptr, bp2, nullptr, nullptr,
        p_m2, NEDGE * NYR, 2048, 128, 2048, 4, 4, 0, BIG);

    // 8. NY-mean + inverse rotation
    k_out<<<NEDGE, 256>>>(p_m2, winv, out);
}